// round 10
// baseline (speedup 1.0000x reference)
#include <cuda_runtime.h>
#include <cuda_bf16.h>
#include <math.h>
#include <stdint.h>

#define BATCH 2
#define SEQ 2048
#define DMODEL 1024
#define NHEAD 16
#define DHEAD 64
#define MROWS (BATCH*SEQ)          // 4096
#define NBIAS (2*SEQ-1)            // 4095

// ---------------- scratch (device globals; allocation-free) ----------------
__device__ __align__(16) __nv_bfloat16 g_ah[(size_t)MROWS*DMODEL];
__device__ __align__(16) __nv_bfloat16 g_al[(size_t)MROWS*DMODEL];
__device__ __align__(16) __nv_bfloat16 g_wh[(size_t)4*DMODEL*DMODEL];
__device__ __align__(16) __nv_bfloat16 g_wl[(size_t)4*DMODEL*DMODEL];
__device__ __align__(16) __nv_bfloat16 g_qh[(size_t)BATCH*NHEAD*SEQ*DHEAD];
__device__ __align__(16) __nv_bfloat16 g_ql[(size_t)BATCH*NHEAD*SEQ*DHEAD];
__device__ __align__(16) __nv_bfloat16 g_kh[(size_t)BATCH*NHEAD*SEQ*DHEAD];
__device__ __align__(16) __nv_bfloat16 g_kl[(size_t)BATCH*NHEAD*SEQ*DHEAD];
__device__ __align__(16) __nv_bfloat16 g_vh[(size_t)BATCH*NHEAD*SEQ*DHEAD];
__device__ __align__(16) __nv_bfloat16 g_vl[(size_t)BATCH*NHEAD*SEQ*DHEAD];
__device__ float g_bias[NHEAD*NBIAS];

// ---------------- helpers ----------------
__device__ __forceinline__ uint32_t smem_u32(const void* p) {
    return (uint32_t)__cvta_generic_to_shared(p);
}
__device__ __forceinline__ void ldm4(uint32_t* r, uint32_t a) {
    asm volatile("ldmatrix.sync.aligned.m8n8.x4.shared.b16 {%0,%1,%2,%3}, [%4];"
        : "=r"(r[0]), "=r"(r[1]), "=r"(r[2]), "=r"(r[3]) : "r"(a));
}
__device__ __forceinline__ void ldm4t(uint32_t* r, uint32_t a) {
    asm volatile("ldmatrix.sync.aligned.m8n8.x4.trans.shared.b16 {%0,%1,%2,%3}, [%4];"
        : "=r"(r[0]), "=r"(r[1]), "=r"(r[2]), "=r"(r[3]) : "r"(a));
}
__device__ __forceinline__ void mma16816(float* c, const uint32_t* a, const uint32_t* b) {
    asm volatile("mma.sync.aligned.m16n8k16.row.col.f32.bf16.bf16.f32 "
        "{%0,%1,%2,%3}, {%4,%5,%6,%7}, {%8,%9}, {%0,%1,%2,%3};"
        : "+f"(c[0]), "+f"(c[1]), "+f"(c[2]), "+f"(c[3])
        : "r"(a[0]), "r"(a[1]), "r"(a[2]), "r"(a[3]), "r"(b[0]), "r"(b[1]));
}
__device__ __forceinline__ uint32_t ldm_addr(const __nv_bfloat16* base, int lds,
                                             int R0, int C0, int lane) {
    return smem_u32(base + (size_t)(R0 + (lane & 15)) * lds + C0 + ((lane >> 4) << 3));
}
__device__ __forceinline__ void pack_split(float x0, float x1, uint32_t& hi, uint32_t& lo) {
    __nv_bfloat16 h0 = __float2bfloat16_rn(x0), h1 = __float2bfloat16_rn(x1);
    hi = ((uint32_t)__bfloat16_as_ushort(h1) << 16) | (uint32_t)__bfloat16_as_ushort(h0);
    __nv_bfloat16 l0 = __float2bfloat16_rn(x0 - __bfloat162float(h0));
    __nv_bfloat16 l1 = __float2bfloat16_rn(x1 - __bfloat162float(h1));
    lo = ((uint32_t)__bfloat16_as_ushort(l1) << 16) | (uint32_t)__bfloat16_as_ushort(l0);
}
__device__ __forceinline__ void cpasync16(uint32_t dst, const void* src) {
    asm volatile("cp.async.cg.shared.global [%0], [%1], 16;" :: "r"(dst), "l"(src));
}
__device__ __forceinline__ void cpcommit() { asm volatile("cp.async.commit_group;"); }
__device__ __forceinline__ void cpwait0()  { asm volatile("cp.async.wait_group 0;"); }

// ---------------- bias table ----------------
__global__ void bias_kernel(const float* __restrict__ rel_emb)
{
    int idx = blockIdx.x * blockDim.x + threadIdx.x;
    if (idx >= NBIAS) return;
    int rel = idx - (SEQ - 1);
    int bucket = (rel > 0) ? 16 : 0;
    int a = rel < 0 ? -rel : rel;
    if (a < 8) {
        bucket += a;
    } else {
        float t = (logf((float)a / 8.0f) / 2.7725887f) * 8.0f;
        int ti = 8 + (int)t;
        bucket += (ti < 15) ? ti : 15;
    }
    #pragma unroll
    for (int h = 0; h < NHEAD; h++)
        g_bias[h * NBIAS + idx] = rel_emb[bucket * NHEAD + h];
}

// ---------------- split hidden -> g_ah/g_al bf16 ----------------
__global__ __launch_bounds__(256) void split_a_kernel(const float* __restrict__ src)
{
    int i = blockIdx.x * blockDim.x + threadIdx.x;
    float4 x = *(const float4*)(src + (size_t)i * 4);
    uint32_t h0, l0, h1, l1;
    pack_split(x.x, x.y, h0, l0);
    pack_split(x.z, x.w, h1, l1);
    uint2 hh = {h0, h1}, ll = {l0, l1};
    *(uint2*)(g_ah + (size_t)i * 4) = hh;
    *(uint2*)(g_al + (size_t)i * 4) = ll;
}

// ---------------- fused transpose + split of all 4 weights ----------------
__global__ __launch_bounds__(256) void wsplit_kernel(const float* __restrict__ W0,
                                                     const float* __restrict__ W1,
                                                     const float* __restrict__ W2,
                                                     const float* __restrict__ W3)
{
    __shared__ float t[32][33];
    int widx = blockIdx.z;
    const float* W = (widx == 0) ? W0 : (widx == 1) ? W1 : (widx == 2) ? W2 : W3;
    int n0 = blockIdx.x * 32, k0 = blockIdx.y * 32;
    int c = threadIdx.x & 31, r4 = (threadIdx.x >> 5) * 4;
    #pragma unroll
    for (int i = 0; i < 4; i++)
        t[r4 + i][c] = W[(size_t)(k0 + r4 + i) * DMODEL + n0 + c];
    __syncthreads();
    __nv_bfloat16* hi = g_wh + (size_t)widx * DMODEL * DMODEL;
    __nv_bfloat16* lo = g_wl + (size_t)widx * DMODEL * DMODEL;
    #pragma unroll
    for (int i = 0; i < 4; i++) {
        float x = t[c][r4 + i];
        __nv_bfloat16 hb = __float2bfloat16_rn(x);
        size_t o = (size_t)(n0 + r4 + i) * DMODEL + k0 + c;
        hi[o] = hb;
        lo[o] = __float2bfloat16_rn(x - __bfloat162float(hb));
    }
}

// ---------------- pipelined mma.sync bf16-split GEMM ----------------
// mode == -1: fused QKV (grid.z = 3); mode == 0: final projection (widx 3), fp32 out
#define GLDS 40
#define GSTAGE (128 * GLDS)                 // elems per buffer
#define GS_BYTES (2 * 4 * GSTAGE * 2)       // 2 stages x 4 buffers

__global__ __launch_bounds__(256, 2) void mma_gemm(float* __restrict__ outp, int mode)
{
    extern __shared__ __nv_bfloat16 smp[];
    int tid = threadIdx.x, lane = tid & 31, wid = tid >> 5;
    int brow = blockIdx.y, bcol = blockIdx.x;
    int wm = wid & 1, wn = wid >> 1;
    int widx = (mode == -1) ? (int)blockIdx.z : 3;
    int m = (mode == -1) ? (int)blockIdx.z + 1 : 0;

    const __nv_bfloat16* srcs[4];
    srcs[0] = g_ah + (size_t)brow * 128 * DMODEL;
    srcs[1] = g_al + (size_t)brow * 128 * DMODEL;
    srcs[2] = g_wh + (size_t)widx * DMODEL * DMODEL + (size_t)bcol * 128 * DMODEL;
    srcs[3] = g_wl + (size_t)widx * DMODEL * DMODEL + (size_t)bcol * 128 * DMODEL;

    int lbuf[8], lrow[8], lseg[8];
    #pragma unroll
    for (int t = 0; t < 8; t++) {
        int gid = tid + t * 256;
        lbuf[t] = gid >> 9; lrow[t] = (gid >> 2) & 127; lseg[t] = gid & 3;
    }

    float acc[4][4][4];
    #pragma unroll
    for (int i = 0; i < 4; i++)
        #pragma unroll
        for (int j = 0; j < 4; j++)
            #pragma unroll
            for (int k = 0; k < 4; k++) acc[i][j][k] = 0.f;

    #pragma unroll
    for (int t = 0; t < 8; t++) {
        uint32_t dst = smem_u32(&smp[lbuf[t] * GSTAGE + lrow[t] * GLDS + lseg[t] * 8]);
        cpasync16(dst, srcs[lbuf[t]] + (size_t)lrow[t] * DMODEL + lseg[t] * 8);
    }
    cpcommit();

    for (int it = 0; it < DMODEL / 32; it++) {
        int s = it & 1;
        cpwait0();
        __syncthreads();
        if (it + 1 < DMODEL / 32) {
            int k0 = (it + 1) * 32;
            #pragma unroll
            for (int t = 0; t < 8; t++) {
                uint32_t dst = smem_u32(&smp[(s ^ 1) * 4 * GSTAGE + lbuf[t] * GSTAGE + lrow[t] * GLDS + lseg[t] * 8]);
                cpasync16(dst, srcs[lbuf[t]] + (size_t)lrow[t] * DMODEL + k0 + lseg[t] * 8);
            }
            cpcommit();
        }

        const __nv_bfloat16* sm = smp + s * 4 * GSTAGE;
        #pragma unroll
        for (int ks = 0; ks < 2; ks++) {
            uint32_t ah[4][4], al[4][4];
            #pragma unroll
            for (int mt = 0; mt < 4; mt++) {
                uint32_t a = ldm_addr(sm, GLDS, wm * 64 + mt * 16, ks * 16, lane);
                ldm4(ah[mt], a);
                ldm4(al[mt], a + GSTAGE * 2);
            }
            #pragma unroll
            for (int ng = 0; ng < 2; ng++) {
                uint32_t bm[4], bl4[4];
                uint32_t ba = ldm_addr(sm + 2 * GSTAGE, GLDS, wn * 32 + ng * 16, ks * 16, lane);
                ldm4(bm, ba);
                ldm4(bl4, ba + GSTAGE * 2);
                uint32_t bh0[2] = {bm[0], bm[2]},  bh1[2] = {bm[1], bm[3]};
                uint32_t bl0[2] = {bl4[0], bl4[2]}, bl1[2] = {bl4[1], bl4[3]};
                // term-major issue: same-acc reuse distance = 8 (was 1)
                #pragma unroll
                for (int mt = 0; mt < 4; mt++) {
                    mma16816(acc[mt][ng * 2 + 0], ah[mt], bh0);
                    mma16816(acc[mt][ng * 2 + 1], ah[mt], bh1);
                }
                #pragma unroll
                for (int mt = 0; mt < 4; mt++) {
                    mma16816(acc[mt][ng * 2 + 0], al[mt], bh0);
                    mma16816(acc[mt][ng * 2 + 1], al[mt], bh1);
                }
                #pragma unroll
                for (int mt = 0; mt < 4; mt++) {
                    mma16816(acc[mt][ng * 2 + 0], ah[mt], bl0);
                    mma16816(acc[mt][ng * 2 + 1], ah[mt], bl1);
                }
            }
        }
    }

    int g = lane >> 2, t2 = (lane & 3) * 2;
    __nv_bfloat16* dh = (m == 1) ? g_qh : (m == 2) ? g_kh : g_vh;
    __nv_bfloat16* dl = (m == 1) ? g_ql : (m == 2) ? g_kl : g_vl;
    #pragma unroll
    for (int mt = 0; mt < 4; mt++) {
        #pragma unroll
        for (int nt = 0; nt < 4; nt++) {
            int r0  = brow * 128 + wm * 64 + mt * 16 + g;
            int col = bcol * 128 + wn * 32 + nt * 8 + t2;
            float c0 = acc[mt][nt][0], c1 = acc[mt][nt][1];
            float c2 = acc[mt][nt][2], c3 = acc[mt][nt][3];
            if (m == 0) {
                float2 p0 = {c0, c1}, p1 = {c2, c3};
                *(float2*)(outp + (size_t)r0 * DMODEL + col) = p0;
                *(float2*)(outp + (size_t)(r0 + 8) * DMODEL + col) = p1;
            } else {
                int hh = col >> 6, d = col & 63;
                #pragma unroll
                for (int rr = 0; rr < 2; rr++) {
                    int r = r0 + rr * 8;
                    int b = r >> 11, s = r & (SEQ - 1);
                    size_t o = (((size_t)(b * NHEAD + hh) * SEQ) + s) * DHEAD + d;
                    uint32_t hv, lv;
                    pack_split(rr ? c2 : c0, rr ? c3 : c1, hv, lv);
                    *(uint32_t*)(dh + o) = hv;
                    *(uint32_t*)(dl + o) = lv;
                }
            }
        }
    }
}

// ---------------- pipelined mma.sync flash attention ----------------
#define QLDS 72
#define KVSTAGE (4 * 64 * QLDS)   // elems per stage (Kh|Kl|Vh|Vl)
#define ATT_SMEM (2*128*QLDS*2 + 2*KVSTAGE*2 + 2*192*4)

__global__ __launch_bounds__(256, 2) void mma_attn()
{
    extern __shared__ char smemraw[];
    __nv_bfloat16* sQh = (__nv_bfloat16*)smemraw;          // 128 x 72
    __nv_bfloat16* sQl = sQh + 128 * QLDS;
    __nv_bfloat16* sKV = sQl + 128 * QLDS;                 // 2 stages x (Kh|Kl|Vh|Vl)
    float* sBias = (float*)(sKV + 2 * KVSTAGE);            // 2 x 192

    int tid = threadIdx.x, lane = tid & 31, wid = tid >> 5;
    int b = blockIdx.z, h = blockIdx.y, q0 = blockIdx.x * 128;
    size_t bh = (size_t)(b * NHEAD + h) * SEQ;

    const __nv_bfloat16* kvsrc[4] = {g_kh, g_kl, g_vh, g_vl};

    // load Q tile (hi/lo), once
    #pragma unroll
    for (int t = 0; t < 8; t++) {
        int gid = tid + t * 256;
        int buf = gid >> 10, rem = gid & 1023, row = rem >> 3, seg = rem & 7;
        const __nv_bfloat16* src = (buf ? g_ql : g_qh) + (bh + q0 + row) * DHEAD + seg * 8;
        *(uint4*)((buf ? sQl : sQh) + row * QLDS + seg * 8) = *(const uint4*)src;
    }

    int vbuf[8], vrow[8], vseg[8];
    #pragma unroll
    for (int t = 0; t < 8; t++) {
        int gid = tid + t * 256;
        vbuf[t] = gid >> 9; vrow[t] = (gid >> 3) & 63; vseg[t] = gid & 7;
    }

    // prologue: KV tile 0 into stage 0, bias tile 0
    #pragma unroll
    for (int t = 0; t < 8; t++) {
        uint32_t dst = smem_u32(sKV + vbuf[t] * (64 * QLDS) + vrow[t] * QLDS + vseg[t] * 8);
        cpasync16(dst, kvsrc[vbuf[t]] + (bh + vrow[t]) * DHEAD + vseg[t] * 8);
    }
    cpcommit();
    if (tid < 191)
        sBias[tid] = g_bias[h * NBIAS + (SEQ - 1) - q0 - 127 + tid];
    __syncthreads();

    // persistent Q fragments (hi and lo)
    uint32_t qh[4][4], ql[4][4];
    #pragma unroll
    for (int ks = 0; ks < 4; ks++) {
        uint32_t a = ldm_addr(sQh, QLDS, wid * 16, ks * 16, lane);
        ldm4(qh[ks], a);
        ldm4(ql[ks], a + 128 * QLDS * 2);
    }

    int g = lane >> 2, t2 = (lane & 3) * 2;
    int qloc0 = wid * 16 + g, qloc1 = qloc0 + 8;
    float m0 = -1e30f, m1 = -1e30f, l0 = 0.f, l1 = 0.f;
    float acco[8][4];
    #pragma unroll
    for (int i = 0; i < 8; i++)
        #pragma unroll
        for (int j = 0; j < 4; j++) acco[i][j] = 0.f;

    for (int kb = 0; kb < SEQ / 64; kb++) {
        int s = kb & 1;
        cpwait0();
        __syncthreads();
        if (kb + 1 < SEQ / 64) {
            #pragma unroll
            for (int t = 0; t < 8; t++) {
                uint32_t dst = smem_u32(sKV + (s ^ 1) * KVSTAGE + vbuf[t] * (64 * QLDS) + vrow[t] * QLDS + vseg[t] * 8);
                cpasync16(dst, kvsrc[vbuf[t]] + (bh + (kb + 1) * 64 + vrow[t]) * DHEAD + vseg[t] * 8);
            }
            cpcommit();
            if (tid < 191)
                sBias[(s ^ 1) * 192 + tid] = g_bias[h * NBIAS + (SEQ - 1) + (kb + 1) * 64 - q0 - 127 + tid];
        }

        const __nv_bfloat16* sKh = sKV + s * KVSTAGE;
        const float* bias = sBias + s * 192;

        float accs[8][4];
        #pragma unroll
        for (int i = 0; i < 8; i++)
            #pragma unroll
            for (int j = 0; j < 4; j++) accs[i][j] = 0.f;

        // ---- scores = Q K^T: process K-tiles in pairs, term-major within pair ----
        #pragma unroll
        for (int ks = 0; ks < 4; ks++) {
            #pragma unroll
            for (int np = 0; np < 2; np++) {          // ng pairs (0,1) and (2,3)
                uint32_t km0[4], kl0_4[4], km1[4], kl1_4[4];
                uint32_t ka0 = ldm_addr(sKh, QLDS, (np * 2 + 0) * 16, ks * 16, lane);
                uint32_t ka1 = ldm_addr(sKh, QLDS, (np * 2 + 1) * 16, ks * 16, lane);
                ldm4(km0, ka0); ldm4(kl0_4, ka0 + 64 * QLDS * 2);
                ldm4(km1, ka1); ldm4(kl1_4, ka1 + 64 * QLDS * 2);
                uint32_t kh00[2] = {km0[0], km0[2]},  kh01[2] = {km0[1], km0[3]};
                uint32_t kh10[2] = {km1[0], km1[2]},  kh11[2] = {km1[1], km1[3]};
                uint32_t kl00[2] = {kl0_4[0], kl0_4[2]}, kl01[2] = {kl0_4[1], kl0_4[3]};
                uint32_t kl10[2] = {kl1_4[0], kl1_4[2]}, kl11[2] = {kl1_4[1], kl1_4[3]};
                float* a0 = accs[np * 4 + 0];
                float* a1 = accs[np * 4 + 1];
                float* a2 = accs[np * 4 + 2];
                float* a3 = accs[np * 4 + 3];
                // term-major: 4 distinct accumulators between same-acc reuses
                mma16816(a0, qh[ks], kh00);
                mma16816(a1, qh[ks], kh01);
                mma16816(a2, qh[ks], kh10);
                mma16816(a3, qh[ks], kh11);
                mma16816(a0, ql[ks], kh00);
                mma16816(a1, ql[ks], kh01);
                mma16816(a2, ql[ks], kh10);
                mma16816(a3, ql[ks], kh11);
                mma16816(a0, qh[ks], kl00);
                mma16816(a1, qh[ks], kl01);
                mma16816(a2, qh[ks], kl10);
                mma16816(a3, qh[ks], kl11);
            }
        }

        float rmax0 = -1e30f, rmax1 = -1e30f;
        #pragma unroll
        for (int nt = 0; nt < 8; nt++) {
            int c = nt * 8 + t2;
            accs[nt][0] += bias[c + 127 - qloc0];
            accs[nt][1] += bias[c + 128 - qloc0];
            accs[nt][2] += bias[c + 127 - qloc1];
            accs[nt][3] += bias[c + 128 - qloc1];
            rmax0 = fmaxf(rmax0, fmaxf(accs[nt][0], accs[nt][1]));
            rmax1 = fmaxf(rmax1, fmaxf(accs[nt][2], accs[nt][3]));
        }
        rmax0 = fmaxf(rmax0, __shfl_xor_sync(0xffffffffu, rmax0, 1, 4));
        rmax0 = fmaxf(rmax0, __shfl_xor_sync(0xffffffffu, rmax0, 2, 4));
        rmax1 = fmaxf(rmax1, __shfl_xor_sync(0xffffffffu, rmax1, 1, 4));
        rmax1 = fmaxf(rmax1, __shfl_xor_sync(0xffffffffu, rmax1, 2, 4));
        float mn0 = fmaxf(m0, rmax0), mn1 = fmaxf(m1, rmax1);
        float corr0 = __expf(m0 - mn0), corr1 = __expf(m1 - mn1);
        float sum0 = 0.f, sum1 = 0.f;
        #pragma unroll
        for (int nt = 0; nt < 8; nt++) {
            accs[nt][0] = __expf(accs[nt][0] - mn0);
            accs[nt][1] = __expf(accs[nt][1] - mn0);
            accs[nt][2] = __expf(accs[nt][2] - mn1);
            accs[nt][3] = __expf(accs[nt][3] - mn1);
            sum0 += accs[nt][0] + accs[nt][1];
            sum1 += accs[nt][2] + accs[nt][3];
        }
        sum0 += __shfl_xor_sync(0xffffffffu, sum0, 1, 4);
        sum0 += __shfl_xor_sync(0xffffffffu, sum0, 2, 4);
        sum1 += __shfl_xor_sync(0xffffffffu, sum1, 1, 4);
        sum1 += __shfl_xor_sync(0xffffffffu, sum1, 2, 4);
        m0 = mn0; m1 = mn1;
        l0 = l0 * corr0 + sum0;
        l1 = l1 * corr1 + sum1;
        #pragma unroll
        for (int nt = 0; nt < 8; nt++) {
            acco[nt][0] *= corr0; acco[nt][1] *= corr0;
            acco[nt][2] *= corr1; acco[nt][3] *= corr1;
        }

        // ---- out += P V: V-tiles in pairs, term-major within pair ----
        #pragma unroll
        for (int ks = 0; ks < 4; ks++) {
            uint32_t ph[4], pl[4];
            pack_split(accs[2 * ks][0],     accs[2 * ks][1],     ph[0], pl[0]);
            pack_split(accs[2 * ks][2],     accs[2 * ks][3],     ph[1], pl[1]);
            pack_split(accs[2 * ks + 1][0], accs[2 * ks + 1][1], ph[2], pl[2]);
            pack_split(accs[2 * ks + 1][2], accs[2 * ks + 1][3], ph[3], pl[3]);
            #pragma unroll
            for (int dp = 0; dp < 2; dp++) {          // dg pairs (0,1) and (2,3)
                uint32_t vm0[4], vl0_4[4], vm1[4], vl1_4[4];
                uint32_t va0 = ldm_addr(sKh + 2 * 64 * QLDS, QLDS, ks * 16, (dp * 2 + 0) * 16, lane);
                uint32_t va1 = ldm_addr(sKh + 2 * 64 * QLDS, QLDS, ks * 16, (dp * 2 + 1) * 16, lane);
                ldm4t(vm0, va0); ldm4t(vl0_4, va0 + 64 * QLDS * 2);
                ldm4t(vm1, va1); ldm4t(vl1_4, va1 + 64 * QLDS * 2);
                uint32_t vh00[2] = {vm0[0], vm0[1]},  vh01[2] = {vm0[2], vm0[3]};
                uint32_t vh10[2] = {vm1[0], vm1[1]},  vh11[2] = {vm1[2], vm1[3]};
                uint32_t vl00[2] = {vl0_4[0], vl0_4[1]}, vl01[2] = {vl0_4[2], vl0_4[3]};
                uint32_t vl10[2] = {vl1_4[0], vl1_4[1]}, vl11[2] = {vl1_4[2], vl1_4[3]};
                float* o0 = acco[dp * 4 + 0];
                float* o1 = acco[dp * 4 + 1];
                float* o2 = acco[dp * 4 + 2];
                float* o3 = acco[dp * 4 + 3];
                mma16816(o0, ph, vh00);
                mma16816(o1, ph, vh01);
                mma16816(o2, ph, vh10);
                mma16816(o3, ph, vh11);
                mma16816(o0, pl, vh00);
                mma16816(o1, pl, vh01);
                mma16816(o2, pl, vh10);
                mma16816(o3, pl, vh11);
                mma16816(o0, ph, vl00);
                mma16816(o1, ph, vl01);
                mma16816(o2, ph, vl10);
                mma16816(o3, ph, vl11);
            }
        }
    }

    float inv0 = 1.0f / l0, inv1 = 1.0f / l1;
    int row0 = b * SEQ + q0 + wid * 16 + g;
    #pragma unroll
    for (int dt = 0; dt < 8; dt++) {
        int d = h * DHEAD + dt * 8 + t2;
        uint32_t hv, lv;
        pack_split(acco[dt][0] * inv0, acco[dt][1] * inv0, hv, lv);
        *(uint32_t*)(g_ah + (size_t)row0 * DMODEL + d) = hv;
        *(uint32_t*)(g_al + (size_t)row0 * DMODEL + d) = lv;
        pack_split(acco[dt][2] * inv1, acco[dt][3] * inv1, hv, lv);
        *(uint32_t*)(g_ah + (size_t)(row0 + 8) * DMODEL + d) = hv;
        *(uint32_t*)(g_al + (size_t)(row0 + 8) * DMODEL + d) = lv;
    }
}

// ---------------- launch ----------------
extern "C" void kernel_launch(void* const* d_in, const int* in_sizes, int n_in,
                              void* d_out, int out_size)
{
    const float* hs  = (const float*)d_in[0];
    const float* Wq  = (const float*)d_in[1];
    const float* Wk  = (const float*)d_in[2];
    const float* Wv  = (const float*)d_in[3];
    const float* Wo  = (const float*)d_in[4];
    const float* rel = (const float*)d_in[5];
    float* out = (float*)d_out;

    cudaFuncSetAttribute(mma_gemm, cudaFuncAttributeMaxDynamicSharedMemorySize, GS_BYTES);
    cudaFuncSetAttribute(mma_attn, cudaFuncAttributeMaxDynamicSharedMemorySize, ATT_SMEM);

    bias_kernel<<<16, 256>>>(rel);                                   // launch 0
    split_a_kernel<<<(MROWS * DMODEL) / (256 * 4), 256>>>(hs);       // launch 1
    dim3 wgrid(32, 32, 4);
    wsplit_kernel<<<wgrid, 256>>>(Wq, Wk, Wv, Wo);                   // launch 2

    dim3 qkvgrid(DMODEL / 128, MROWS / 128, 3);                      // (8, 32, 3)
    mma_gemm<<<qkvgrid, 256, GS_BYTES>>>(out, -1);                   // launch 3

    dim3 agrid(SEQ / 128, NHEAD, BATCH);                             // (16, 16, 2)
    mma_attn<<<agrid, 256, ATT_SMEM>>>();                            // launch 4

    dim3 ggrid(DMODEL / 128, MROWS / 128);                           // (8, 32)
    mma_gemm<<<ggrid, 256, GS_BYTES>>>(out, 0);                      // launch 5 <- ncu -s 5 lands here
}

// round 12
// speedup vs baseline: 1.5373x; 1.5373x over previous
#include <cuda_runtime.h>
#include <cuda_bf16.h>
#include <math.h>
#include <stdint.h>

#define BATCH 2
#define SEQ 2048
#define DMODEL 1024
#define NHEAD 16
#define DHEAD 64
#define MROWS (BATCH*SEQ)          // 4096
#define NBIAS (2*SEQ-1)            // 4095

// ---------------- scratch (device globals; allocation-free) ----------------
__device__ __align__(16) __nv_bfloat16 g_ah[(size_t)MROWS*DMODEL];
__device__ __align__(16) __nv_bfloat16 g_al[(size_t)MROWS*DMODEL];
__device__ __align__(16) __nv_bfloat16 g_wh[(size_t)4*DMODEL*DMODEL];
__device__ __align__(16) __nv_bfloat16 g_wl[(size_t)4*DMODEL*DMODEL];
__device__ __align__(16) __nv_bfloat16 g_qh[(size_t)BATCH*NHEAD*SEQ*DHEAD];
__device__ __align__(16) __nv_bfloat16 g_ql[(size_t)BATCH*NHEAD*SEQ*DHEAD];
__device__ __align__(16) __nv_bfloat16 g_kh[(size_t)BATCH*NHEAD*SEQ*DHEAD];
__device__ __align__(16) __nv_bfloat16 g_kl[(size_t)BATCH*NHEAD*SEQ*DHEAD];
__device__ __align__(16) __nv_bfloat16 g_vh[(size_t)BATCH*NHEAD*SEQ*DHEAD];
__device__ __align__(16) __nv_bfloat16 g_vl[(size_t)BATCH*NHEAD*SEQ*DHEAD];
__device__ float g_bias[NHEAD*NBIAS];

// ---------------- helpers ----------------
__device__ __forceinline__ uint32_t smem_u32(const void* p) {
    return (uint32_t)__cvta_generic_to_shared(p);
}
__device__ __forceinline__ void ldm4(uint32_t* r, uint32_t a) {
    asm volatile("ldmatrix.sync.aligned.m8n8.x4.shared.b16 {%0,%1,%2,%3}, [%4];"
        : "=r"(r[0]), "=r"(r[1]), "=r"(r[2]), "=r"(r[3]) : "r"(a));
}
__device__ __forceinline__ void ldm4t(uint32_t* r, uint32_t a) {
    asm volatile("ldmatrix.sync.aligned.m8n8.x4.trans.shared.b16 {%0,%1,%2,%3}, [%4];"
        : "=r"(r[0]), "=r"(r[1]), "=r"(r[2]), "=r"(r[3]) : "r"(a));
}
__device__ __forceinline__ void mma16816(float* c, const uint32_t* a, const uint32_t* b) {
    asm volatile("mma.sync.aligned.m16n8k16.row.col.f32.bf16.bf16.f32 "
        "{%0,%1,%2,%3}, {%4,%5,%6,%7}, {%8,%9}, {%0,%1,%2,%3};"
        : "+f"(c[0]), "+f"(c[1]), "+f"(c[2]), "+f"(c[3])
        : "r"(a[0]), "r"(a[1]), "r"(a[2]), "r"(a[3]), "r"(b[0]), "r"(b[1]));
}
__device__ __forceinline__ uint32_t ldm_addr(const __nv_bfloat16* base, int lds,
                                             int R0, int C0, int lane) {
    return smem_u32(base + (size_t)(R0 + (lane & 15)) * lds + C0 + ((lane >> 4) << 3));
}
__device__ __forceinline__ void pack_split(float x0, float x1, uint32_t& hi, uint32_t& lo) {
    __nv_bfloat16 h0 = __float2bfloat16_rn(x0), h1 = __float2bfloat16_rn(x1);
    hi = ((uint32_t)__bfloat16_as_ushort(h1) << 16) | (uint32_t)__bfloat16_as_ushort(h0);
    __nv_bfloat16 l0 = __float2bfloat16_rn(x0 - __bfloat162float(h0));
    __nv_bfloat16 l1 = __float2bfloat16_rn(x1 - __bfloat162float(h1));
    lo = ((uint32_t)__bfloat16_as_ushort(l1) << 16) | (uint32_t)__bfloat16_as_ushort(l0);
}
__device__ __forceinline__ void cpasync16(uint32_t dst, const void* src) {
    asm volatile("cp.async.cg.shared.global [%0], [%1], 16;" :: "r"(dst), "l"(src));
}
__device__ __forceinline__ void cpcommit() { asm volatile("cp.async.commit_group;"); }
__device__ __forceinline__ void cpwait0()  { asm volatile("cp.async.wait_group 0;"); }

// ---------------- bias table ----------------
__global__ void bias_kernel(const float* __restrict__ rel_emb)
{
    int idx = blockIdx.x * blockDim.x + threadIdx.x;
    if (idx >= NBIAS) return;
    int rel = idx - (SEQ - 1);
    int bucket = (rel > 0) ? 16 : 0;
    int a = rel < 0 ? -rel : rel;
    if (a < 8) {
        bucket += a;
    } else {
        float t = (logf((float)a / 8.0f) / 2.7725887f) * 8.0f;
        int ti = 8 + (int)t;
        bucket += (ti < 15) ? ti : 15;
    }
    #pragma unroll
    for (int h = 0; h < NHEAD; h++)
        g_bias[h * NBIAS + idx] = rel_emb[bucket * NHEAD + h];
}

// ---------------- split hidden -> g_ah/g_al bf16 ----------------
__global__ __launch_bounds__(256) void split_a_kernel(const float* __restrict__ src)
{
    int i = blockIdx.x * blockDim.x + threadIdx.x;
    float4 x = *(const float4*)(src + (size_t)i * 4);
    uint32_t h0, l0, h1, l1;
    pack_split(x.x, x.y, h0, l0);
    pack_split(x.z, x.w, h1, l1);
    uint2 hh = {h0, h1}, ll = {l0, l1};
    *(uint2*)(g_ah + (size_t)i * 4) = hh;
    *(uint2*)(g_al + (size_t)i * 4) = ll;
}

// ---------------- fused transpose + split of all 4 weights ----------------
__global__ __launch_bounds__(256) void wsplit_kernel(const float* __restrict__ W0,
                                                     const float* __restrict__ W1,
                                                     const float* __restrict__ W2,
                                                     const float* __restrict__ W3)
{
    __shared__ float t[32][33];
    int widx = blockIdx.z;
    const float* W = (widx == 0) ? W0 : (widx == 1) ? W1 : (widx == 2) ? W2 : W3;
    int n0 = blockIdx.x * 32, k0 = blockIdx.y * 32;
    int c = threadIdx.x & 31, r4 = (threadIdx.x >> 5) * 4;
    #pragma unroll
    for (int i = 0; i < 4; i++)
        t[r4 + i][c] = W[(size_t)(k0 + r4 + i) * DMODEL + n0 + c];
    __syncthreads();
    __nv_bfloat16* hi = g_wh + (size_t)widx * DMODEL * DMODEL;
    __nv_bfloat16* lo = g_wl + (size_t)widx * DMODEL * DMODEL;
    #pragma unroll
    for (int i = 0; i < 4; i++) {
        float x = t[c][r4 + i];
        __nv_bfloat16 hb = __float2bfloat16_rn(x);
        size_t o = (size_t)(n0 + r4 + i) * DMODEL + k0 + c;
        hi[o] = hb;
        lo[o] = __float2bfloat16_rn(x - __bfloat162float(hb));
    }
}

// ---------------- pipelined mma.sync bf16-split GEMM ----------------
// mode == -1: fused QKV (grid.z = 3); mode == 0: final projection (widx 3), fp32 out
#define GLDS 40
#define GSTAGE (128 * GLDS)                 // elems per buffer
#define GS_BYTES (2 * 4 * GSTAGE * 2)       // 2 stages x 4 buffers

__global__ __launch_bounds__(256, 2) void mma_gemm(float* __restrict__ outp, int mode)
{
    extern __shared__ __nv_bfloat16 smp[];
    int tid = threadIdx.x, lane = tid & 31, wid = tid >> 5;
    int brow = blockIdx.y, bcol = blockIdx.x;
    int wm = wid & 1, wn = wid >> 1;
    int widx = (mode == -1) ? (int)blockIdx.z : 3;
    int m = (mode == -1) ? (int)blockIdx.z + 1 : 0;

    const __nv_bfloat16* srcs[4];
    srcs[0] = g_ah + (size_t)brow * 128 * DMODEL;
    srcs[1] = g_al + (size_t)brow * 128 * DMODEL;
    srcs[2] = g_wh + (size_t)widx * DMODEL * DMODEL + (size_t)bcol * 128 * DMODEL;
    srcs[3] = g_wl + (size_t)widx * DMODEL * DMODEL + (size_t)bcol * 128 * DMODEL;

    int lbuf[8], lrow[8], lseg[8];
    #pragma unroll
    for (int t = 0; t < 8; t++) {
        int gid = tid + t * 256;
        lbuf[t] = gid >> 9; lrow[t] = (gid >> 2) & 127; lseg[t] = gid & 3;
    }

    float acc[4][4][4];
    #pragma unroll
    for (int i = 0; i < 4; i++)
        #pragma unroll
        for (int j = 0; j < 4; j++)
            #pragma unroll
            for (int k = 0; k < 4; k++) acc[i][j][k] = 0.f;

    #pragma unroll
    for (int t = 0; t < 8; t++) {
        uint32_t dst = smem_u32(&smp[lbuf[t] * GSTAGE + lrow[t] * GLDS + lseg[t] * 8]);
        cpasync16(dst, srcs[lbuf[t]] + (size_t)lrow[t] * DMODEL + lseg[t] * 8);
    }
    cpcommit();

    for (int it = 0; it < DMODEL / 32; it++) {
        int s = it & 1;
        cpwait0();
        __syncthreads();
        if (it + 1 < DMODEL / 32) {
            int k0 = (it + 1) * 32;
            #pragma unroll
            for (int t = 0; t < 8; t++) {
                uint32_t dst = smem_u32(&smp[(s ^ 1) * 4 * GSTAGE + lbuf[t] * GSTAGE + lrow[t] * GLDS + lseg[t] * 8]);
                cpasync16(dst, srcs[lbuf[t]] + (size_t)lrow[t] * DMODEL + k0 + lseg[t] * 8);
            }
            cpcommit();
        }

        const __nv_bfloat16* sm = smp + s * 4 * GSTAGE;
        #pragma unroll
        for (int ks = 0; ks < 2; ks++) {
            uint32_t ah[4][4], al[4][4];
            #pragma unroll
            for (int mt = 0; mt < 4; mt++) {
                uint32_t a = ldm_addr(sm, GLDS, wm * 64 + mt * 16, ks * 16, lane);
                ldm4(ah[mt], a);
                ldm4(al[mt], a + GSTAGE * 2);
            }
            #pragma unroll
            for (int ng = 0; ng < 2; ng++) {
                uint32_t bm[4], bl4[4];
                uint32_t ba = ldm_addr(sm + 2 * GSTAGE, GLDS, wn * 32 + ng * 16, ks * 16, lane);
                ldm4(bm, ba);
                ldm4(bl4, ba + GSTAGE * 2);
                uint32_t bh0[2] = {bm[0], bm[2]},  bh1[2] = {bm[1], bm[3]};
                uint32_t bl0[2] = {bl4[0], bl4[2]}, bl1[2] = {bl4[1], bl4[3]};
                // n0/n1 interleave: same-acc reuse distance 2, live set unchanged
                #pragma unroll
                for (int mt = 0; mt < 4; mt++) {
                    mma16816(acc[mt][ng * 2 + 0], ah[mt], bh0);
                    mma16816(acc[mt][ng * 2 + 1], ah[mt], bh1);
                    mma16816(acc[mt][ng * 2 + 0], al[mt], bh0);
                    mma16816(acc[mt][ng * 2 + 1], al[mt], bh1);
                    mma16816(acc[mt][ng * 2 + 0], ah[mt], bl0);
                    mma16816(acc[mt][ng * 2 + 1], ah[mt], bl1);
                }
            }
        }
    }

    int g = lane >> 2, t2 = (lane & 3) * 2;
    __nv_bfloat16* dh = (m == 1) ? g_qh : (m == 2) ? g_kh : g_vh;
    __nv_bfloat16* dl = (m == 1) ? g_ql : (m == 2) ? g_kl : g_vl;
    #pragma unroll
    for (int mt = 0; mt < 4; mt++) {
        #pragma unroll
        for (int nt = 0; nt < 4; nt++) {
            int r0  = brow * 128 + wm * 64 + mt * 16 + g;
            int col = bcol * 128 + wn * 32 + nt * 8 + t2;
            float c0 = acc[mt][nt][0], c1 = acc[mt][nt][1];
            float c2 = acc[mt][nt][2], c3 = acc[mt][nt][3];
            if (m == 0) {
                float2 p0 = {c0, c1}, p1 = {c2, c3};
                *(float2*)(outp + (size_t)r0 * DMODEL + col) = p0;
                *(float2*)(outp + (size_t)(r0 + 8) * DMODEL + col) = p1;
            } else {
                int hh = col >> 6, d = col & 63;
                #pragma unroll
                for (int rr = 0; rr < 2; rr++) {
                    int r = r0 + rr * 8;
                    int b = r >> 11, s = r & (SEQ - 1);
                    size_t o = (((size_t)(b * NHEAD + hh) * SEQ) + s) * DHEAD + d;
                    uint32_t hv, lv;
                    pack_split(rr ? c2 : c0, rr ? c3 : c1, hv, lv);
                    *(uint32_t*)(dh + o) = hv;
                    *(uint32_t*)(dl + o) = lv;
                }
            }
        }
    }
}

// ---------------- pipelined mma.sync flash attention ----------------
#define QLDS 72
#define KVSTAGE (4 * 64 * QLDS)   // elems per stage (Kh|Kl|Vh|Vl)
#define ATT_SMEM (2*128*QLDS*2 + 2*KVSTAGE*2 + 2*192*4)

__global__ __launch_bounds__(256, 2) void mma_attn()
{
    extern __shared__ char smemraw[];
    __nv_bfloat16* sQh = (__nv_bfloat16*)smemraw;          // 128 x 72
    __nv_bfloat16* sQl = sQh + 128 * QLDS;
    __nv_bfloat16* sKV = sQl + 128 * QLDS;                 // 2 stages x (Kh|Kl|Vh|Vl)
    float* sBias = (float*)(sKV + 2 * KVSTAGE);            // 2 x 192

    int tid = threadIdx.x, lane = tid & 31, wid = tid >> 5;
    int b = blockIdx.z, h = blockIdx.y, q0 = blockIdx.x * 128;
    size_t bh = (size_t)(b * NHEAD + h) * SEQ;

    const __nv_bfloat16* kvsrc[4] = {g_kh, g_kl, g_vh, g_vl};

    // load Q tile (hi/lo), once
    #pragma unroll
    for (int t = 0; t < 8; t++) {
        int gid = tid + t * 256;
        int buf = gid >> 10, rem = gid & 1023, row = rem >> 3, seg = rem & 7;
        const __nv_bfloat16* src = (buf ? g_ql : g_qh) + (bh + q0 + row) * DHEAD + seg * 8;
        *(uint4*)((buf ? sQl : sQh) + row * QLDS + seg * 8) = *(const uint4*)src;
    }

    int vbuf[8], vrow[8], vseg[8];
    #pragma unroll
    for (int t = 0; t < 8; t++) {
        int gid = tid + t * 256;
        vbuf[t] = gid >> 9; vrow[t] = (gid >> 3) & 63; vseg[t] = gid & 7;
    }

    // prologue: KV tile 0 into stage 0, bias tile 0
    #pragma unroll
    for (int t = 0; t < 8; t++) {
        uint32_t dst = smem_u32(sKV + vbuf[t] * (64 * QLDS) + vrow[t] * QLDS + vseg[t] * 8);
        cpasync16(dst, kvsrc[vbuf[t]] + (bh + vrow[t]) * DHEAD + vseg[t] * 8);
    }
    cpcommit();
    if (tid < 191)
        sBias[tid] = g_bias[h * NBIAS + (SEQ - 1) - q0 - 127 + tid];
    __syncthreads();

    // persistent Q fragments (hi and lo)
    uint32_t qh[4][4], ql[4][4];
    #pragma unroll
    for (int ks = 0; ks < 4; ks++) {
        uint32_t a = ldm_addr(sQh, QLDS, wid * 16, ks * 16, lane);
        ldm4(qh[ks], a);
        ldm4(ql[ks], a + 128 * QLDS * 2);
    }

    int g = lane >> 2, t2 = (lane & 3) * 2;
    int qloc0 = wid * 16 + g, qloc1 = qloc0 + 8;
    float m0 = -1e30f, m1 = -1e30f, l0 = 0.f, l1 = 0.f;
    float acco[8][4];
    #pragma unroll
    for (int i = 0; i < 8; i++)
        #pragma unroll
        for (int j = 0; j < 4; j++) acco[i][j] = 0.f;

    for (int kb = 0; kb < SEQ / 64; kb++) {
        int s = kb & 1;
        cpwait0();
        __syncthreads();
        if (kb + 1 < SEQ / 64) {
            #pragma unroll
            for (int t = 0; t < 8; t++) {
                uint32_t dst = smem_u32(sKV + (s ^ 1) * KVSTAGE + vbuf[t] * (64 * QLDS) + vrow[t] * QLDS + vseg[t] * 8);
                cpasync16(dst, kvsrc[vbuf[t]] + (bh + (kb + 1) * 64 + vrow[t]) * DHEAD + vseg[t] * 8);
            }
            cpcommit();
            if (tid < 191)
                sBias[(s ^ 1) * 192 + tid] = g_bias[h * NBIAS + (SEQ - 1) + (kb + 1) * 64 - q0 - 127 + tid];
        }

        const __nv_bfloat16* sKh = sKV + s * KVSTAGE;
        const float* bias = sBias + s * 192;

        float accs[8][4];
        #pragma unroll
        for (int i = 0; i < 8; i++)
            #pragma unroll
            for (int j = 0; j < 4; j++) accs[i][j] = 0.f;

        #pragma unroll
        for (int ks = 0; ks < 4; ks++) {
            #pragma unroll
            for (int ng = 0; ng < 4; ng++) {
                uint32_t km[4], kl4[4];
                uint32_t ka = ldm_addr(sKh, QLDS, ng * 16, ks * 16, lane);
                ldm4(km, ka);
                ldm4(kl4, ka + 64 * QLDS * 2);
                uint32_t kh0[2] = {km[0], km[2]},  kh1[2] = {km[1], km[3]};
                uint32_t kl0[2] = {kl4[0], kl4[2]}, kl1[2] = {kl4[1], kl4[3]};
                // n0/n1 interleave, distance 2
                mma16816(accs[ng * 2 + 0], qh[ks], kh0);
                mma16816(accs[ng * 2 + 1], qh[ks], kh1);
                mma16816(accs[ng * 2 + 0], ql[ks], kh0);
                mma16816(accs[ng * 2 + 1], ql[ks], kh1);
                mma16816(accs[ng * 2 + 0], qh[ks], kl0);
                mma16816(accs[ng * 2 + 1], qh[ks], kl1);
            }
        }

        float rmax0 = -1e30f, rmax1 = -1e30f;
        #pragma unroll
        for (int nt = 0; nt < 8; nt++) {
            int c = nt * 8 + t2;
            accs[nt][0] += bias[c + 127 - qloc0];
            accs[nt][1] += bias[c + 128 - qloc0];
            accs[nt][2] += bias[c + 127 - qloc1];
            accs[nt][3] += bias[c + 128 - qloc1];
            rmax0 = fmaxf(rmax0, fmaxf(accs[nt][0], accs[nt][1]));
            rmax1 = fmaxf(rmax1, fmaxf(accs[nt][2], accs[nt][3]));
        }
        rmax0 = fmaxf(rmax0, __shfl_xor_sync(0xffffffffu, rmax0, 1, 4));
        rmax0 = fmaxf(rmax0, __shfl_xor_sync(0xffffffffu, rmax0, 2, 4));
        rmax1 = fmaxf(rmax1, __shfl_xor_sync(0xffffffffu, rmax1, 1, 4));
        rmax1 = fmaxf(rmax1, __shfl_xor_sync(0xffffffffu, rmax1, 2, 4));
        float mn0 = fmaxf(m0, rmax0), mn1 = fmaxf(m1, rmax1);
        float corr0 = __expf(m0 - mn0), corr1 = __expf(m1 - mn1);
        float sum0 = 0.f, sum1 = 0.f;
        #pragma unroll
        for (int nt = 0; nt < 8; nt++) {
            accs[nt][0] = __expf(accs[nt][0] - mn0);
            accs[nt][1] = __expf(accs[nt][1] - mn0);
            accs[nt][2] = __expf(accs[nt][2] - mn1);
            accs[nt][3] = __expf(accs[nt][3] - mn1);
            sum0 += accs[nt][0] + accs[nt][1];
            sum1 += accs[nt][2] + accs[nt][3];
        }
        sum0 += __shfl_xor_sync(0xffffffffu, sum0, 1, 4);
        sum0 += __shfl_xor_sync(0xffffffffu, sum0, 2, 4);
        sum1 += __shfl_xor_sync(0xffffffffu, sum1, 1, 4);
        sum1 += __shfl_xor_sync(0xffffffffu, sum1, 2, 4);
        m0 = mn0; m1 = mn1;
        l0 = l0 * corr0 + sum0;
        l1 = l1 * corr1 + sum1;
        #pragma unroll
        for (int nt = 0; nt < 8; nt++) {
            acco[nt][0] *= corr0; acco[nt][1] *= corr0;
            acco[nt][2] *= corr1; acco[nt][3] *= corr1;
        }

        #pragma unroll
        for (int ks = 0; ks < 4; ks++) {
            uint32_t ph[4], pl[4];
            pack_split(accs[2 * ks][0],     accs[2 * ks][1],     ph[0], pl[0]);
            pack_split(accs[2 * ks][2],     accs[2 * ks][3],     ph[1], pl[1]);
            pack_split(accs[2 * ks + 1][0], accs[2 * ks + 1][1], ph[2], pl[2]);
            pack_split(accs[2 * ks + 1][2], accs[2 * ks + 1][3], ph[3], pl[3]);
            #pragma unroll
            for (int dg = 0; dg < 4; dg++) {
                uint32_t vm[4], vl4[4];
                uint32_t va = ldm_addr(sKh + 2 * 64 * QLDS, QLDS, ks * 16, dg * 16, lane);
                ldm4t(vm, va);
                ldm4t(vl4, va + 64 * QLDS * 2);
                uint32_t vh0[2] = {vm[0], vm[1]},  vh1[2] = {vm[2], vm[3]};
                uint32_t vl0[2] = {vl4[0], vl4[1]}, vl1[2] = {vl4[2], vl4[3]};
                // n0/n1 interleave, distance 2
                mma16816(acco[dg * 2 + 0], ph, vh0);
                mma16816(acco[dg * 2 + 1], ph, vh1);
                mma16816(acco[dg * 2 + 0], pl, vh0);
                mma16816(acco[dg * 2 + 1], pl, vh1);
                mma16816(acco[dg * 2 + 0], ph, vl0);
                mma16816(acco[dg * 2 + 1], ph, vl1);
            }
        }
    }

    float inv0 = 1.0f / l0, inv1 = 1.0f / l1;
    int row0 = b * SEQ + q0 + wid * 16 + g;
    #pragma unroll
    for (int dt = 0; dt < 8; dt++) {
        int d = h * DHEAD + dt * 8 + t2;
        uint32_t hv, lv;
        pack_split(acco[dt][0] * inv0, acco[dt][1] * inv0, hv, lv);
        *(uint32_t*)(g_ah + (size_t)row0 * DMODEL + d) = hv;
        *(uint32_t*)(g_al + (size_t)row0 * DMODEL + d) = lv;
        pack_split(acco[dt][2] * inv1, acco[dt][3] * inv1, hv, lv);
        *(uint32_t*)(g_ah + (size_t)(row0 + 8) * DMODEL + d) = hv;
        *(uint32_t*)(g_al + (size_t)(row0 + 8) * DMODEL + d) = lv;
    }
}

// ---------------- launch ----------------
extern "C" void kernel_launch(void* const* d_in, const int* in_sizes, int n_in,
                              void* d_out, int out_size)
{
    const float* hs  = (const float*)d_in[0];
    const float* Wq  = (const float*)d_in[1];
    const float* Wk  = (const float*)d_in[2];
    const float* Wv  = (const float*)d_in[3];
    const float* Wo  = (const float*)d_in[4];
    const float* rel = (const float*)d_in[5];
    float* out = (float*)d_out;

    cudaFuncSetAttribute(mma_gemm, cudaFuncAttributeMaxDynamicSharedMemorySize, GS_BYTES);
    cudaFuncSetAttribute(mma_attn, cudaFuncAttributeMaxDynamicSharedMemorySize, ATT_SMEM);

    bias_kernel<<<16, 256>>>(rel);                                   // launch 0
    split_a_kernel<<<(MROWS * DMODEL) / (256 * 4), 256>>>(hs);       // launch 1
    dim3 wgrid(32, 32, 4);
    wsplit_kernel<<<wgrid, 256>>>(Wq, Wk, Wv, Wo);                   // launch 2

    dim3 qkvgrid(DMODEL / 128, MROWS / 128, 3);                      // (8, 32, 3)
    mma_gemm<<<qkvgrid, 256, GS_BYTES>>>(out, -1);                   // launch 3

    dim3 agrid(SEQ / 128, NHEAD, BATCH);                             // (16, 16, 2)
    mma_attn<<<agrid, 256, ATT_SMEM>>>();                            // launch 4

    dim3 ggrid(DMODEL / 128, MROWS / 128);                           // (8, 32)
    mma_gemm<<<ggrid, 256, GS_BYTES>>>(out, 0);                      // launch 5 <- ncu -s 5 lands here
}

// round 14
// speedup vs baseline: 1.7579x; 1.1435x over previous
#include <cuda_runtime.h>
#include <cuda_bf16.h>
#include <cuda_fp16.h>
#include <math.h>
#include <stdint.h>

#define BATCH 2
#define SEQ 2048
#define DMODEL 1024
#define NHEAD 16
#define DHEAD 64
#define MROWS (BATCH*SEQ)          // 4096
#define NBIAS (2*SEQ-1)            // 4095

// ---------------- scratch (device globals; allocation-free) ----------------
__device__ __align__(16) __nv_bfloat16 g_ah[(size_t)MROWS*DMODEL];   // hidden bf16 hi
__device__ __align__(16) __nv_bfloat16 g_al[(size_t)MROWS*DMODEL];   // hidden bf16 lo
__device__ __align__(16) __half        g_fh[(size_t)MROWS*DMODEL];   // hidden fp16 hi
__device__ __align__(16) __half        g_fl[(size_t)MROWS*DMODEL];   // hidden fp16 lo
__device__ __align__(16) __nv_bfloat16 g_wh[(size_t)2*DMODEL*DMODEL]; // Wq,Wk ^T bf16 hi
__device__ __align__(16) __nv_bfloat16 g_wl[(size_t)2*DMODEL*DMODEL]; // Wq,Wk ^T bf16 lo
__device__ __align__(16) __half        g_wvh[(size_t)DMODEL*DMODEL];  // Wv^T fp16 hi
__device__ __align__(16) __half        g_woh[(size_t)DMODEL*DMODEL];  // Wo^T fp16 hi
__device__ __align__(16) __nv_bfloat16 g_qh[(size_t)BATCH*NHEAD*SEQ*DHEAD];
__device__ __align__(16) __nv_bfloat16 g_ql[(size_t)BATCH*NHEAD*SEQ*DHEAD];
__device__ __align__(16) __nv_bfloat16 g_kh[(size_t)BATCH*NHEAD*SEQ*DHEAD];
__device__ __align__(16) __nv_bfloat16 g_kl[(size_t)BATCH*NHEAD*SEQ*DHEAD];
__device__ __align__(16) __half        g_vh[(size_t)BATCH*NHEAD*SEQ*DHEAD]; // fp16, no lo
__device__ __align__(16) __half        g_oh[(size_t)MROWS*DMODEL];   // attn out fp16 hi
__device__ __align__(16) __half        g_ol[(size_t)MROWS*DMODEL];   // attn out fp16 lo
__device__ float g_bias[NHEAD*NBIAS];

// ---------------- helpers ----------------
__device__ __forceinline__ uint32_t smem_u32(const void* p) {
    return (uint32_t)__cvta_generic_to_shared(p);
}
__device__ __forceinline__ void ldm4(uint32_t* r, uint32_t a) {
    asm volatile("ldmatrix.sync.aligned.m8n8.x4.shared.b16 {%0,%1,%2,%3}, [%4];"
        : "=r"(r[0]), "=r"(r[1]), "=r"(r[2]), "=r"(r[3]) : "r"(a));
}
__device__ __forceinline__ void ldm4t(uint32_t* r, uint32_t a) {
    asm volatile("ldmatrix.sync.aligned.m8n8.x4.trans.shared.b16 {%0,%1,%2,%3}, [%4];"
        : "=r"(r[0]), "=r"(r[1]), "=r"(r[2]), "=r"(r[3]) : "r"(a));
}
__device__ __forceinline__ void mma16816(float* c, const uint32_t* a, const uint32_t* b) {
    asm volatile("mma.sync.aligned.m16n8k16.row.col.f32.bf16.bf16.f32 "
        "{%0,%1,%2,%3}, {%4,%5,%6,%7}, {%8,%9}, {%0,%1,%2,%3};"
        : "+f"(c[0]), "+f"(c[1]), "+f"(c[2]), "+f"(c[3])
        : "r"(a[0]), "r"(a[1]), "r"(a[2]), "r"(a[3]), "r"(b[0]), "r"(b[1]));
}
__device__ __forceinline__ void mma16816h(float* c, const uint32_t* a, const uint32_t* b) {
    asm volatile("mma.sync.aligned.m16n8k16.row.col.f32.f16.f16.f32 "
        "{%0,%1,%2,%3}, {%4,%5,%6,%7}, {%8,%9}, {%0,%1,%2,%3};"
        : "+f"(c[0]), "+f"(c[1]), "+f"(c[2]), "+f"(c[3])
        : "r"(a[0]), "r"(a[1]), "r"(a[2]), "r"(a[3]), "r"(b[0]), "r"(b[1]));
}
__device__ __forceinline__ uint32_t ldm_addr2(const void* base, int lds,
                                              int R0, int C0, int lane) {
    return smem_u32((const __nv_bfloat16*)base + (size_t)(R0 + (lane & 15)) * lds + C0 + ((lane >> 4) << 3));
}
__device__ __forceinline__ void pack_split(float x0, float x1, uint32_t& hi, uint32_t& lo) {
    __nv_bfloat16 h0 = __float2bfloat16_rn(x0), h1 = __float2bfloat16_rn(x1);
    hi = ((uint32_t)__bfloat16_as_ushort(h1) << 16) | (uint32_t)__bfloat16_as_ushort(h0);
    __nv_bfloat16 l0 = __float2bfloat16_rn(x0 - __bfloat162float(h0));
    __nv_bfloat16 l1 = __float2bfloat16_rn(x1 - __bfloat162float(h1));
    lo = ((uint32_t)__bfloat16_as_ushort(l1) << 16) | (uint32_t)__bfloat16_as_ushort(l0);
}
__device__ __forceinline__ void pack_split_h(float x0, float x1, uint32_t& hi, uint32_t& lo) {
    __half h0 = __float2half_rn(x0), h1 = __float2half_rn(x1);
    hi = ((uint32_t)__half_as_ushort(h1) << 16) | (uint32_t)__half_as_ushort(h0);
    __half l0 = __float2half_rn(x0 - __half2float(h0));
    __half l1 = __float2half_rn(x1 - __half2float(h1));
    lo = ((uint32_t)__half_as_ushort(l1) << 16) | (uint32_t)__half_as_ushort(l0);
}
__device__ __forceinline__ void cpasync16(uint32_t dst, const void* src) {
    asm volatile("cp.async.cg.shared.global [%0], [%1], 16;" :: "r"(dst), "l"(src));
}
__device__ __forceinline__ void cpcommit() { asm volatile("cp.async.commit_group;"); }
__device__ __forceinline__ void cpwait0()  { asm volatile("cp.async.wait_group 0;"); }

// ---------------- bias table ----------------
__global__ void bias_kernel(const float* __restrict__ rel_emb)
{
    int idx = blockIdx.x * blockDim.x + threadIdx.x;
    if (idx >= NBIAS) return;
    int rel = idx - (SEQ - 1);
    int bucket = (rel > 0) ? 16 : 0;
    int a = rel < 0 ? -rel : rel;
    if (a < 8) {
        bucket += a;
    } else {
        float t = (logf((float)a / 8.0f) / 2.7725887f) * 8.0f;
        int ti = 8 + (int)t;
        bucket += (ti < 15) ? ti : 15;
    }
    #pragma unroll
    for (int h = 0; h < NHEAD; h++)
        g_bias[h * NBIAS + idx] = rel_emb[bucket * NHEAD + h];
}

// ---------------- split hidden -> bf16 hi/lo AND fp16 hi/lo ----------------
__global__ __launch_bounds__(256) void split_a_kernel(const float* __restrict__ src)
{
    int i = blockIdx.x * blockDim.x + threadIdx.x;
    float4 x = *(const float4*)(src + (size_t)i * 4);
    uint32_t h0, l0, h1, l1;
    pack_split(x.x, x.y, h0, l0);
    pack_split(x.z, x.w, h1, l1);
    uint2 hh = {h0, h1}, ll = {l0, l1};
    *(uint2*)(g_ah + (size_t)i * 4) = hh;
    *(uint2*)(g_al + (size_t)i * 4) = ll;
    pack_split_h(x.x, x.y, h0, l0);
    pack_split_h(x.z, x.w, h1, l1);
    uint2 fh = {h0, h1}, fl = {l0, l1};
    *(uint2*)(g_fh + (size_t)i * 4) = fh;
    *(uint2*)(g_fl + (size_t)i * 4) = fl;
}

// ---------------- transpose + split weights ----------------
// z=0,1: Wq,Wk -> bf16 hi/lo; z=2: Wv -> fp16 hi; z=3: Wo -> fp16 hi
__global__ __launch_bounds__(256) void wsplit_kernel(const float* __restrict__ W0,
                                                     const float* __restrict__ W1,
                                                     const float* __restrict__ W2,
                                                     const float* __restrict__ W3)
{
    __shared__ float t[32][33];
    int widx = blockIdx.z;
    const float* W = (widx == 0) ? W0 : (widx == 1) ? W1 : (widx == 2) ? W2 : W3;
    int n0 = blockIdx.x * 32, k0 = blockIdx.y * 32;
    int c = threadIdx.x & 31, r4 = (threadIdx.x >> 5) * 4;
    #pragma unroll
    for (int i = 0; i < 4; i++)
        t[r4 + i][c] = W[(size_t)(k0 + r4 + i) * DMODEL + n0 + c];
    __syncthreads();
    if (widx < 2) {
        __nv_bfloat16* hi = g_wh + (size_t)widx * DMODEL * DMODEL;
        __nv_bfloat16* lo = g_wl + (size_t)widx * DMODEL * DMODEL;
        #pragma unroll
        for (int i = 0; i < 4; i++) {
            float x = t[c][r4 + i];
            __nv_bfloat16 hb = __float2bfloat16_rn(x);
            size_t o = (size_t)(n0 + r4 + i) * DMODEL + k0 + c;
            hi[o] = hb;
            lo[o] = __float2bfloat16_rn(x - __bfloat162float(hb));
        }
    } else {
        __half* hi = (widx == 2) ? g_wvh : g_woh;
        #pragma unroll
        for (int i = 0; i < 4; i++) {
            float x = t[c][r4 + i];
            size_t o = (size_t)(n0 + r4 + i) * DMODEL + k0 + c;
            hi[o] = __float2half_rn(x);
        }
    }
}

// ---------------- bf16 3-term GEMM (Wq, Wk; grid.z = 2) ----------------
#define GLDS 40
#define GSTAGE (128 * GLDS)
#define GS_BYTES_BF (2 * 4 * GSTAGE * 2)

__global__ __launch_bounds__(256, 2) void mma_gemm_bf()
{
    extern __shared__ __nv_bfloat16 smp[];
    int tid = threadIdx.x, lane = tid & 31, wid = tid >> 5;
    int brow = blockIdx.y, bcol = blockIdx.x;
    int wm = wid & 1, wn = wid >> 1;
    int widx = blockIdx.z;            // 0=Wq, 1=Wk

    const __nv_bfloat16* srcs[4];
    srcs[0] = g_ah + (size_t)brow * 128 * DMODEL;
    srcs[1] = g_al + (size_t)brow * 128 * DMODEL;
    srcs[2] = g_wh + (size_t)widx * DMODEL * DMODEL + (size_t)bcol * 128 * DMODEL;
    srcs[3] = g_wl + (size_t)widx * DMODEL * DMODEL + (size_t)bcol * 128 * DMODEL;

    int lbuf[8], lrow[8], lseg[8];
    #pragma unroll
    for (int t = 0; t < 8; t++) {
        int gid = tid + t * 256;
        lbuf[t] = gid >> 9; lrow[t] = (gid >> 2) & 127; lseg[t] = gid & 3;
    }

    float acc[4][4][4];
    #pragma unroll
    for (int i = 0; i < 4; i++)
        #pragma unroll
        for (int j = 0; j < 4; j++)
            #pragma unroll
            for (int k = 0; k < 4; k++) acc[i][j][k] = 0.f;

    #pragma unroll
    for (int t = 0; t < 8; t++) {
        uint32_t dst = smem_u32(&smp[lbuf[t] * GSTAGE + lrow[t] * GLDS + lseg[t] * 8]);
        cpasync16(dst, srcs[lbuf[t]] + (size_t)lrow[t] * DMODEL + lseg[t] * 8);
    }
    cpcommit();

    for (int it = 0; it < DMODEL / 32; it++) {
        int s = it & 1;
        cpwait0();
        __syncthreads();
        if (it + 1 < DMODEL / 32) {
            int k0 = (it + 1) * 32;
            #pragma unroll
            for (int t = 0; t < 8; t++) {
                uint32_t dst = smem_u32(&smp[(s ^ 1) * 4 * GSTAGE + lbuf[t] * GSTAGE + lrow[t] * GLDS + lseg[t] * 8]);
                cpasync16(dst, srcs[lbuf[t]] + (size_t)lrow[t] * DMODEL + k0 + lseg[t] * 8);
            }
            cpcommit();
        }

        const __nv_bfloat16* sm = smp + s * 4 * GSTAGE;
        #pragma unroll
        for (int ks = 0; ks < 2; ks++) {
            uint32_t ah[4][4], al[4][4];
            #pragma unroll
            for (int mt = 0; mt < 4; mt++) {
                uint32_t a = ldm_addr2(sm, GLDS, wm * 64 + mt * 16, ks * 16, lane);
                ldm4(ah[mt], a);
                ldm4(al[mt], a + GSTAGE * 2);
            }
            #pragma unroll
            for (int ng = 0; ng < 2; ng++) {
                uint32_t bm[4], bl4[4];
                uint32_t ba = ldm_addr2(sm + 2 * GSTAGE, GLDS, wn * 32 + ng * 16, ks * 16, lane);
                ldm4(bm, ba);
                ldm4(bl4, ba + GSTAGE * 2);
                uint32_t bh0[2] = {bm[0], bm[2]},  bh1[2] = {bm[1], bm[3]};
                uint32_t bl0[2] = {bl4[0], bl4[2]}, bl1[2] = {bl4[1], bl4[3]};
                #pragma unroll
                for (int mt = 0; mt < 4; mt++) {
                    mma16816(acc[mt][ng * 2 + 0], ah[mt], bh0);
                    mma16816(acc[mt][ng * 2 + 1], ah[mt], bh1);
                    mma16816(acc[mt][ng * 2 + 0], al[mt], bh0);
                    mma16816(acc[mt][ng * 2 + 1], al[mt], bh1);
                    mma16816(acc[mt][ng * 2 + 0], ah[mt], bl0);
                    mma16816(acc[mt][ng * 2 + 1], ah[mt], bl1);
                }
            }
        }
    }

    int g = lane >> 2, t2 = (lane & 3) * 2;
    __nv_bfloat16* dh = (widx == 0) ? g_qh : g_kh;
    __nv_bfloat16* dl = (widx == 0) ? g_ql : g_kl;
    #pragma unroll
    for (int mt = 0; mt < 4; mt++) {
        #pragma unroll
        for (int nt = 0; nt < 4; nt++) {
            int r0  = brow * 128 + wm * 64 + mt * 16 + g;
            int col = bcol * 128 + wn * 32 + nt * 8 + t2;
            int hh = col >> 6, d = col & 63;
            #pragma unroll
            for (int rr = 0; rr < 2; rr++) {
                int r = r0 + rr * 8;
                int b = r >> 11, s = r & (SEQ - 1);
                size_t o = (((size_t)(b * NHEAD + hh) * SEQ) + s) * DHEAD + d;
                uint32_t hv, lv;
                pack_split(acc[mt][nt][rr * 2], acc[mt][nt][rr * 2 + 1], hv, lv);
                *(uint32_t*)(dh + o) = hv;
                *(uint32_t*)(dl + o) = lv;
            }
        }
    }
}

// ---------------- fp16 2-term GEMM (Wv: which=0 -> fp16 v; Wo: which=1 -> fp32 out) ----------------
#define GS_BYTES_H (2 * 3 * GSTAGE * 2)

__global__ __launch_bounds__(256, 2) void mma_gemm_h(float* __restrict__ outp, int which)
{
    extern __shared__ __half smh[];
    int tid = threadIdx.x, lane = tid & 31, wid = tid >> 5;
    int brow = blockIdx.y, bcol = blockIdx.x;
    int wm = wid & 1, wn = wid >> 1;

    const __half* srcs[3];
    srcs[0] = (which ? g_oh : g_fh) + (size_t)brow * 128 * DMODEL;
    srcs[1] = (which ? g_ol : g_fl) + (size_t)brow * 128 * DMODEL;
    srcs[2] = (which ? g_woh : g_wvh) + (size_t)bcol * 128 * DMODEL;

    int lbuf[6], lrow[6], lseg[6];
    #pragma unroll
    for (int t = 0; t < 6; t++) {
        int gid = tid + t * 256;                  // 1536 slots = 3 bufs x 128 rows x 4 segs
        lbuf[t] = gid >> 9; lrow[t] = (gid >> 2) & 127; lseg[t] = gid & 3;
    }

    float acc[4][4][4];
    #pragma unroll
    for (int i = 0; i < 4; i++)
        #pragma unroll
        for (int j = 0; j < 4; j++)
            #pragma unroll
            for (int k = 0; k < 4; k++) acc[i][j][k] = 0.f;

    #pragma unroll
    for (int t = 0; t < 6; t++) {
        uint32_t dst = smem_u32(&smh[lbuf[t] * GSTAGE + lrow[t] * GLDS + lseg[t] * 8]);
        cpasync16(dst, srcs[lbuf[t]] + (size_t)lrow[t] * DMODEL + lseg[t] * 8);
    }
    cpcommit();

    for (int it = 0; it < DMODEL / 32; it++) {
        int s = it & 1;
        cpwait0();
        __syncthreads();
        if (it + 1 < DMODEL / 32) {
            int k0 = (it + 1) * 32;
            #pragma unroll
            for (int t = 0; t < 6; t++) {
                uint32_t dst = smem_u32(&smh[(s ^ 1) * 3 * GSTAGE + lbuf[t] * GSTAGE + lrow[t] * GLDS + lseg[t] * 8]);
                cpasync16(dst, srcs[lbuf[t]] + (size_t)lrow[t] * DMODEL + k0 + lseg[t] * 8);
            }
            cpcommit();
        }

        const __half* sm = smh + s * 3 * GSTAGE;
        #pragma unroll
        for (int ks = 0; ks < 2; ks++) {
            uint32_t ah[4][4], al[4][4];
            #pragma unroll
            for (int mt = 0; mt < 4; mt++) {
                uint32_t a = ldm_addr2(sm, GLDS, wm * 64 + mt * 16, ks * 16, lane);
                ldm4(ah[mt], a);
                ldm4(al[mt], a + GSTAGE * 2);
            }
            #pragma unroll
            for (int ng = 0; ng < 2; ng++) {
                uint32_t bm[4];
                uint32_t ba = ldm_addr2(sm + 2 * GSTAGE, GLDS, wn * 32 + ng * 16, ks * 16, lane);
                ldm4(bm, ba);
                uint32_t bh0[2] = {bm[0], bm[2]}, bh1[2] = {bm[1], bm[3]};
                #pragma unroll
                for (int mt = 0; mt < 4; mt++) {
                    mma16816h(acc[mt][ng * 2 + 0], ah[mt], bh0);
                    mma16816h(acc[mt][ng * 2 + 1], ah[mt], bh1);
                    mma16816h(acc[mt][ng * 2 + 0], al[mt], bh0);
                    mma16816h(acc[mt][ng * 2 + 1], al[mt], bh1);
                }
            }
        }
    }

    int g = lane >> 2, t2 = (lane & 3) * 2;
    #pragma unroll
    for (int mt = 0; mt < 4; mt++) {
        #pragma unroll
        for (int nt = 0; nt < 4; nt++) {
            int r0  = brow * 128 + wm * 64 + mt * 16 + g;
            int col = bcol * 128 + wn * 32 + nt * 8 + t2;
            if (which == 1) {
                float2 p0 = {acc[mt][nt][0], acc[mt][nt][1]};
                float2 p1 = {acc[mt][nt][2], acc[mt][nt][3]};
                *(float2*)(outp + (size_t)r0 * DMODEL + col) = p0;
                *(float2*)(outp + (size_t)(r0 + 8) * DMODEL + col) = p1;
            } else {
                int hh = col >> 6, d = col & 63;
                #pragma unroll
                for (int rr = 0; rr < 2; rr++) {
                    int r = r0 + rr * 8;
                    int b = r >> 11, s = r & (SEQ - 1);
                    size_t o = (((size_t)(b * NHEAD + hh) * SEQ) + s) * DHEAD + d;
                    __half2 v = __floats2half2_rn(acc[mt][nt][rr * 2], acc[mt][nt][rr * 2 + 1]);
                    *(__half2*)(g_vh + o) = v;
                }
            }
        }
    }
}

// ---------------- flash attention: QK bf16 3-term, PV fp16 2-term ----------------
#define QLDS 72
#define KVSTAGE (3 * 64 * QLDS)   // Kh | Kl | Vh
#define ATT_SMEM (2*128*QLDS*2 + 2*KVSTAGE*2 + 2*192*4)

__global__ __launch_bounds__(256, 2) void mma_attn()
{
    extern __shared__ char smemraw[];
    __nv_bfloat16* sQh = (__nv_bfloat16*)smemraw;          // 128 x 72
    __nv_bfloat16* sQl = sQh + 128 * QLDS;
    __nv_bfloat16* sKV = sQl + 128 * QLDS;                 // 2 stages x (Kh|Kl|Vh)
    float* sBias = (float*)(sKV + 2 * KVSTAGE);            // 2 x 192

    int tid = threadIdx.x, lane = tid & 31, wid = tid >> 5;
    int b = blockIdx.z, h = blockIdx.y, q0 = blockIdx.x * 128;
    size_t bh = (size_t)(b * NHEAD + h) * SEQ;

    const void* kvsrc[3] = {(const void*)g_kh, (const void*)g_kl, (const void*)g_vh};

    // load Q tile (hi/lo), once
    #pragma unroll
    for (int t = 0; t < 8; t++) {
        int gid = tid + t * 256;
        int buf = gid >> 10, rem = gid & 1023, row = rem >> 3, seg = rem & 7;
        const __nv_bfloat16* src = (buf ? g_ql : g_qh) + (bh + q0 + row) * DHEAD + seg * 8;
        *(uint4*)((buf ? sQl : sQh) + row * QLDS + seg * 8) = *(const uint4*)src;
    }

    int vbuf[6], vrow[6], vseg[6];
    #pragma unroll
    for (int t = 0; t < 6; t++) {
        int gid = tid + t * 256;                  // 1536 = 3 bufs x 64 rows x 8 segs
        vbuf[t] = gid >> 9; vrow[t] = (gid >> 3) & 63; vseg[t] = gid & 7;
    }

    // prologue: KV tile 0 into stage 0, bias tile 0
    #pragma unroll
    for (int t = 0; t < 6; t++) {
        uint32_t dst = smem_u32(sKV + vbuf[t] * (64 * QLDS) + vrow[t] * QLDS + vseg[t] * 8);
        cpasync16(dst, (const __nv_bfloat16*)kvsrc[vbuf[t]] + (bh + vrow[t]) * DHEAD + vseg[t] * 8);
    }
    cpcommit();
    if (tid < 191)
        sBias[tid] = g_bias[h * NBIAS + (SEQ - 1) - q0 - 127 + tid];
    __syncthreads();

    uint32_t qh[4][4], ql[4][4];
    #pragma unroll
    for (int ks = 0; ks < 4; ks++) {
        uint32_t a = ldm_addr2(sQh, QLDS, wid * 16, ks * 16, lane);
        ldm4(qh[ks], a);
        ldm4(ql[ks], a + 128 * QLDS * 2);
    }

    int g = lane >> 2, t2 = (lane & 3) * 2;
    int qloc0 = wid * 16 + g, qloc1 = qloc0 + 8;
    float m0 = -1e30f, m1 = -1e30f, l0 = 0.f, l1 = 0.f;
    float acco[8][4];
    #pragma unroll
    for (int i = 0; i < 8; i++)
        #pragma unroll
        for (int j = 0; j < 4; j++) acco[i][j] = 0.f;

    for (int kb = 0; kb < SEQ / 64; kb++) {
        int s = kb & 1;
        cpwait0();
        __syncthreads();
        if (kb + 1 < SEQ / 64) {
            #pragma unroll
            for (int t = 0; t < 6; t++) {
                uint32_t dst = smem_u32(sKV + (s ^ 1) * KVSTAGE + vbuf[t] * (64 * QLDS) + vrow[t] * QLDS + vseg[t] * 8);
                cpasync16(dst, (const __nv_bfloat16*)kvsrc[vbuf[t]] + (bh + (kb + 1) * 64 + vrow[t]) * DHEAD + vseg[t] * 8);
            }
            cpcommit();
            if (tid < 191)
                sBias[(s ^ 1) * 192 + tid] = g_bias[h * NBIAS + (SEQ - 1) + (kb + 1) * 64 - q0 - 127 + tid];
        }

        const __nv_bfloat16* sKh = sKV + s * KVSTAGE;
        const float* bias = sBias + s * 192;

        float accs[8][4];
        #pragma unroll
        for (int i = 0; i < 8; i++)
            #pragma unroll
            for (int j = 0; j < 4; j++) accs[i][j] = 0.f;

        // ---- scores = Q K^T (bf16 3-term) ----
        #pragma unroll
        for (int ks = 0; ks < 4; ks++) {
            #pragma unroll
            for (int ng = 0; ng < 4; ng++) {
                uint32_t km[4], kl4[4];
                uint32_t ka = ldm_addr2(sKh, QLDS, ng * 16, ks * 16, lane);
                ldm4(km, ka);
                ldm4(kl4, ka + 64 * QLDS * 2);
                uint32_t kh0[2] = {km[0], km[2]},  kh1[2] = {km[1], km[3]};
                uint32_t kl0[2] = {kl4[0], kl4[2]}, kl1[2] = {kl4[1], kl4[3]};
                mma16816(accs[ng * 2 + 0], qh[ks], kh0);
                mma16816(accs[ng * 2 + 1], qh[ks], kh1);
                mma16816(accs[ng * 2 + 0], ql[ks], kh0);
                mma16816(accs[ng * 2 + 1], ql[ks], kh1);
                mma16816(accs[ng * 2 + 0], qh[ks], kl0);
                mma16816(accs[ng * 2 + 1], qh[ks], kl1);
            }
        }

        // ---- bias + online softmax ----
        float rmax0 = -1e30f, rmax1 = -1e30f;
        #pragma unroll
        for (int nt = 0; nt < 8; nt++) {
            int c = nt * 8 + t2;
            accs[nt][0] += bias[c + 127 - qloc0];
            accs[nt][1] += bias[c + 128 - qloc0];
            accs[nt][2] += bias[c + 127 - qloc1];
            accs[nt][3] += bias[c + 128 - qloc1];
            rmax0 = fmaxf(rmax0, fmaxf(accs[nt][0], accs[nt][1]));
            rmax1 = fmaxf(rmax1, fmaxf(accs[nt][2], accs[nt][3]));
        }
        rmax0 = fmaxf(rmax0, __shfl_xor_sync(0xffffffffu, rmax0, 1, 4));
        rmax0 = fmaxf(rmax0, __shfl_xor_sync(0xffffffffu, rmax0, 2, 4));
        rmax1 = fmaxf(rmax1, __shfl_xor_sync(0xffffffffu, rmax1, 1, 4));
        rmax1 = fmaxf(rmax1, __shfl_xor_sync(0xffffffffu, rmax1, 2, 4));
        float mn0 = fmaxf(m0, rmax0), mn1 = fmaxf(m1, rmax1);
        float corr0 = __expf(m0 - mn0), corr1 = __expf(m1 - mn1);
        float sum0 = 0.f, sum1 = 0.f;
        #pragma unroll
        for (int nt = 0; nt < 8; nt++) {
            accs[nt][0] = __expf(accs[nt][0] - mn0);
            accs[nt][1] = __expf(accs[nt][1] - mn0);
            accs[nt][2] = __expf(accs[nt][2] - mn1);
            accs[nt][3] = __expf(accs[nt][3] - mn1);
            sum0 += accs[nt][0] + accs[nt][1];
            sum1 += accs[nt][2] + accs[nt][3];
        }
        sum0 += __shfl_xor_sync(0xffffffffu, sum0, 1, 4);
        sum0 += __shfl_xor_sync(0xffffffffu, sum0, 2, 4);
        sum1 += __shfl_xor_sync(0xffffffffu, sum1, 1, 4);
        sum1 += __shfl_xor_sync(0xffffffffu, sum1, 2, 4);
        m0 = mn0; m1 = mn1;
        l0 = l0 * corr0 + sum0;
        l1 = l1 * corr1 + sum1;
        #pragma unroll
        for (int nt = 0; nt < 8; nt++) {
            acco[nt][0] *= corr0; acco[nt][1] *= corr0;
            acco[nt][2] *= corr1; acco[nt][3] *= corr1;
        }

        // ---- out += P V (fp16 2-term: (ph+pl) x vh) ----
        const __nv_bfloat16* sVh = sKh + 2 * 64 * QLDS;
        #pragma unroll
        for (int ks = 0; ks < 4; ks++) {
            uint32_t ph[4], pl[4];
            pack_split_h(accs[2 * ks][0],     accs[2 * ks][1],     ph[0], pl[0]);
            pack_split_h(accs[2 * ks][2],     accs[2 * ks][3],     ph[1], pl[1]);
            pack_split_h(accs[2 * ks + 1][0], accs[2 * ks + 1][1], ph[2], pl[2]);
            pack_split_h(accs[2 * ks + 1][2], accs[2 * ks + 1][3], ph[3], pl[3]);
            #pragma unroll
            for (int dg = 0; dg < 4; dg++) {
                uint32_t vm[4];
                uint32_t va = ldm_addr2(sVh, QLDS, ks * 16, dg * 16, lane);
                ldm4t(vm, va);
                uint32_t vh0[2] = {vm[0], vm[1]}, vh1[2] = {vm[2], vm[3]};
                mma16816h(acco[dg * 2 + 0], ph, vh0);
                mma16816h(acco[dg * 2 + 1], ph, vh1);
                mma16816h(acco[dg * 2 + 0], pl, vh0);
                mma16816h(acco[dg * 2 + 1], pl, vh1);
            }
        }
    }

    // epilogue: normalize, fp16 split to g_oh/g_ol
    float inv0 = 1.0f / l0, inv1 = 1.0f / l1;
    int row0 = b * SEQ + q0 + wid * 16 + g;
    #pragma unroll
    for (int dt = 0; dt < 8; dt++) {
        int d = h * DHEAD + dt * 8 + t2;
        uint32_t hv, lv;
        pack_split_h(acco[dt][0] * inv0, acco[dt][1] * inv0, hv, lv);
        *(uint32_t*)(g_oh + (size_t)row0 * DMODEL + d) = hv;
        *(uint32_t*)(g_ol + (size_t)row0 * DMODEL + d) = lv;
        pack_split_h(acco[dt][2] * inv1, acco[dt][3] * inv1, hv, lv);
        *(uint32_t*)(g_oh + (size_t)(row0 + 8) * DMODEL + d) = hv;
        *(uint32_t*)(g_ol + (size_t)(row0 + 8) * DMODEL + d) = lv;
    }
}

// ---------------- launch ----------------
extern "C" void kernel_launch(void* const* d_in, const int* in_sizes, int n_in,
                              void* d_out, int out_size)
{
    const float* hs  = (const float*)d_in[0];
    const float* Wq  = (const float*)d_in[1];
    const float* Wk  = (const float*)d_in[2];
    const float* Wv  = (const float*)d_in[3];
    const float* Wo  = (const float*)d_in[4];
    const float* rel = (const float*)d_in[5];
    float* out = (float*)d_out;

    cudaFuncSetAttribute(mma_gemm_bf, cudaFuncAttributeMaxDynamicSharedMemorySize, GS_BYTES_BF);
    cudaFuncSetAttribute(mma_gemm_h,  cudaFuncAttributeMaxDynamicSharedMemorySize, GS_BYTES_H);
    cudaFuncSetAttribute(mma_attn,    cudaFuncAttributeMaxDynamicSharedMemorySize, ATT_SMEM);

    bias_kernel<<<16, 256>>>(rel);                                   // launch 0
    split_a_kernel<<<(MROWS * DMODEL) / (256 * 4), 256>>>(hs);       // launch 1
    dim3 wgrid(32, 32, 4);
    wsplit_kernel<<<wgrid, 256>>>(Wq, Wk, Wv, Wo);                   // launch 2

    dim3 qkgrid(DMODEL / 128, MROWS / 128, 2);                       // (8, 32, 2)
    mma_gemm_bf<<<qkgrid, 256, GS_BYTES_BF>>>();                     // launch 3: Wq,Wk

    dim3 ggrid(DMODEL / 128, MROWS / 128);                           // (8, 32)
    mma_gemm_h<<<ggrid, 256, GS_BYTES_H>>>(out, 0);                  // launch 4: Wv -> fp16 v

    dim3 agrid(SEQ / 128, NHEAD, BATCH);                             // (16, 16, 2)
    mma_attn<<<agrid, 256, ATT_SMEM>>>();                            // launch 5 <- ncu lands HERE

    mma_gemm_h<<<ggrid, 256, GS_BYTES_H>>>(out, 1);                  // launch 6: Wo -> fp32 out
}

// round 15
// speedup vs baseline: 1.7701x; 1.0070x over previous
#include <cuda_runtime.h>
#include <cuda_bf16.h>
#include <cuda_fp16.h>
#include <math.h>
#include <stdint.h>

#define BATCH 2
#define SEQ 2048
#define DMODEL 1024
#define NHEAD 16
#define DHEAD 64
#define MROWS (BATCH*SEQ)          // 4096
#define NBIAS (2*SEQ-1)            // 4095

// ---------------- scratch (device globals; allocation-free) ----------------
__device__ __align__(16) __nv_bfloat16 g_ah[(size_t)MROWS*DMODEL];   // hidden bf16 hi
__device__ __align__(16) __nv_bfloat16 g_al[(size_t)MROWS*DMODEL];   // hidden bf16 lo
__device__ __align__(16) __half        g_fh[(size_t)MROWS*DMODEL];   // hidden fp16 hi
__device__ __align__(16) __half        g_fl[(size_t)MROWS*DMODEL];   // hidden fp16 lo
__device__ __align__(16) __nv_bfloat16 g_wh[(size_t)2*DMODEL*DMODEL]; // Wq,Wk ^T bf16 hi
__device__ __align__(16) __nv_bfloat16 g_wl[(size_t)2*DMODEL*DMODEL]; // Wq,Wk ^T bf16 lo
__device__ __align__(16) __half        g_wvh[(size_t)DMODEL*DMODEL];  // Wv^T fp16 hi
__device__ __align__(16) __half        g_woh[(size_t)DMODEL*DMODEL];  // Wo^T fp16 hi
__device__ __align__(16) __nv_bfloat16 g_qh[(size_t)BATCH*NHEAD*SEQ*DHEAD];
__device__ __align__(16) __nv_bfloat16 g_ql[(size_t)BATCH*NHEAD*SEQ*DHEAD];
__device__ __align__(16) __nv_bfloat16 g_kh[(size_t)BATCH*NHEAD*SEQ*DHEAD];
__device__ __align__(16) __nv_bfloat16 g_kl[(size_t)BATCH*NHEAD*SEQ*DHEAD];
__device__ __align__(16) __half        g_vh[(size_t)BATCH*NHEAD*SEQ*DHEAD]; // fp16, no lo
__device__ __align__(16) __half        g_oh[(size_t)MROWS*DMODEL];   // attn out fp16 hi
__device__ __align__(16) __half        g_ol[(size_t)MROWS*DMODEL];   // attn out fp16 lo
__device__ float g_bias[NHEAD*NBIAS];

// ---------------- helpers ----------------
__device__ __forceinline__ uint32_t smem_u32(const void* p) {
    return (uint32_t)__cvta_generic_to_shared(p);
}
__device__ __forceinline__ void ldm4(uint32_t* r, uint32_t a) {
    asm volatile("ldmatrix.sync.aligned.m8n8.x4.shared.b16 {%0,%1,%2,%3}, [%4];"
        : "=r"(r[0]), "=r"(r[1]), "=r"(r[2]), "=r"(r[3]) : "r"(a));
}
__device__ __forceinline__ void ldm4t(uint32_t* r, uint32_t a) {
    asm volatile("ldmatrix.sync.aligned.m8n8.x4.trans.shared.b16 {%0,%1,%2,%3}, [%4];"
        : "=r"(r[0]), "=r"(r[1]), "=r"(r[2]), "=r"(r[3]) : "r"(a));
}
__device__ __forceinline__ void mma16816(float* c, const uint32_t* a, const uint32_t* b) {
    asm volatile("mma.sync.aligned.m16n8k16.row.col.f32.bf16.bf16.f32 "
        "{%0,%1,%2,%3}, {%4,%5,%6,%7}, {%8,%9}, {%0,%1,%2,%3};"
        : "+f"(c[0]), "+f"(c[1]), "+f"(c[2]), "+f"(c[3])
        : "r"(a[0]), "r"(a[1]), "r"(a[2]), "r"(a[3]), "r"(b[0]), "r"(b[1]));
}
__device__ __forceinline__ void mma16816h(float* c, const uint32_t* a, const uint32_t* b) {
    asm volatile("mma.sync.aligned.m16n8k16.row.col.f32.f16.f16.f32 "
        "{%0,%1,%2,%3}, {%4,%5,%6,%7}, {%8,%9}, {%0,%1,%2,%3};"
        : "+f"(c[0]), "+f"(c[1]), "+f"(c[2]), "+f"(c[3])
        : "r"(a[0]), "r"(a[1]), "r"(a[2]), "r"(a[3]), "r"(b[0]), "r"(b[1]));
}
__device__ __forceinline__ uint32_t ldm_addr2(const void* base, int lds,
                                              int R0, int C0, int lane) {
    return smem_u32((const __nv_bfloat16*)base + (size_t)(R0 + (lane & 15)) * lds + C0 + ((lane >> 4) << 3));
}
__device__ __forceinline__ void pack_split(float x0, float x1, uint32_t& hi, uint32_t& lo) {
    __nv_bfloat16 h0 = __float2bfloat16_rn(x0), h1 = __float2bfloat16_rn(x1);
    hi = ((uint32_t)__bfloat16_as_ushort(h1) << 16) | (uint32_t)__bfloat16_as_ushort(h0);
    __nv_bfloat16 l0 = __float2bfloat16_rn(x0 - __bfloat162float(h0));
    __nv_bfloat16 l1 = __float2bfloat16_rn(x1 - __bfloat162float(h1));
    lo = ((uint32_t)__bfloat16_as_ushort(l1) << 16) | (uint32_t)__bfloat16_as_ushort(l0);
}
__device__ __forceinline__ void pack_split_h(float x0, float x1, uint32_t& hi, uint32_t& lo) {
    __half h0 = __float2half_rn(x0), h1 = __float2half_rn(x1);
    hi = ((uint32_t)__half_as_ushort(h1) << 16) | (uint32_t)__half_as_ushort(h0);
    __half l0 = __float2half_rn(x0 - __half2float(h0));
    __half l1 = __float2half_rn(x1 - __half2float(h1));
    lo = ((uint32_t)__half_as_ushort(l1) << 16) | (uint32_t)__half_as_ushort(l0);
}
__device__ __forceinline__ void cpasync16(uint32_t dst, const void* src) {
    asm volatile("cp.async.cg.shared.global [%0], [%1], 16;" :: "r"(dst), "l"(src));
}
__device__ __forceinline__ void cpcommit() { asm volatile("cp.async.commit_group;"); }
__device__ __forceinline__ void cpwait0()  { asm volatile("cp.async.wait_group 0;"); }

// ---------------- bias table ----------------
__global__ void bias_kernel(const float* __restrict__ rel_emb)
{
    int idx = blockIdx.x * blockDim.x + threadIdx.x;
    if (idx >= NBIAS) return;
    int rel = idx - (SEQ - 1);
    int bucket = (rel > 0) ? 16 : 0;
    int a = rel < 0 ? -rel : rel;
    if (a < 8) {
        bucket += a;
    } else {
        float t = (logf((float)a / 8.0f) / 2.7725887f) * 8.0f;
        int ti = 8 + (int)t;
        bucket += (ti < 15) ? ti : 15;
    }
    #pragma unroll
    for (int h = 0; h < NHEAD; h++)
        g_bias[h * NBIAS + idx] = rel_emb[bucket * NHEAD + h];
}

// ---------------- split hidden -> bf16 hi/lo AND fp16 hi/lo ----------------
__global__ __launch_bounds__(256) void split_a_kernel(const float* __restrict__ src)
{
    int i = blockIdx.x * blockDim.x + threadIdx.x;
    float4 x = *(const float4*)(src + (size_t)i * 4);
    uint32_t h0, l0, h1, l1;
    pack_split(x.x, x.y, h0, l0);
    pack_split(x.z, x.w, h1, l1);
    uint2 hh = {h0, h1}, ll = {l0, l1};
    *(uint2*)(g_ah + (size_t)i * 4) = hh;
    *(uint2*)(g_al + (size_t)i * 4) = ll;
    pack_split_h(x.x, x.y, h0, l0);
    pack_split_h(x.z, x.w, h1, l1);
    uint2 fh = {h0, h1}, fl = {l0, l1};
    *(uint2*)(g_fh + (size_t)i * 4) = fh;
    *(uint2*)(g_fl + (size_t)i * 4) = fl;
}

// ---------------- transpose + split weights ----------------
__global__ __launch_bounds__(256) void wsplit_kernel(const float* __restrict__ W0,
                                                     const float* __restrict__ W1,
                                                     const float* __restrict__ W2,
                                                     const float* __restrict__ W3)
{
    __shared__ float t[32][33];
    int widx = blockIdx.z;
    const float* W = (widx == 0) ? W0 : (widx == 1) ? W1 : (widx == 2) ? W2 : W3;
    int n0 = blockIdx.x * 32, k0 = blockIdx.y * 32;
    int c = threadIdx.x & 31, r4 = (threadIdx.x >> 5) * 4;
    #pragma unroll
    for (int i = 0; i < 4; i++)
        t[r4 + i][c] = W[(size_t)(k0 + r4 + i) * DMODEL + n0 + c];
    __syncthreads();
    if (widx < 2) {
        __nv_bfloat16* hi = g_wh + (size_t)widx * DMODEL * DMODEL;
        __nv_bfloat16* lo = g_wl + (size_t)widx * DMODEL * DMODEL;
        #pragma unroll
        for (int i = 0; i < 4; i++) {
            float x = t[c][r4 + i];
            __nv_bfloat16 hb = __float2bfloat16_rn(x);
            size_t o = (size_t)(n0 + r4 + i) * DMODEL + k0 + c;
            hi[o] = hb;
            lo[o] = __float2bfloat16_rn(x - __bfloat162float(hb));
        }
    } else {
        __half* hi = (widx == 2) ? g_wvh : g_woh;
        #pragma unroll
        for (int i = 0; i < 4; i++) {
            float x = t[c][r4 + i];
            size_t o = (size_t)(n0 + r4 + i) * DMODEL + k0 + c;
            hi[o] = __float2half_rn(x);
        }
    }
}

// ---------------- bf16 3-term GEMM v2: CTA 128x64, warp 32x32, 3 CTAs/SM ----------------
#define GLDS 40
// stage layout (rows of GLDS elems): Ah[0..127] | Al[128..255] | Bh[256..319] | Bl[320..383]
#define BF_STAGE (384 * GLDS)                 // elems
#define GS2_BF (2 * BF_STAGE * 2)             // bytes

__global__ __launch_bounds__(256, 3) void mma_gemm_bf()
{
    extern __shared__ __nv_bfloat16 smp[];
    int tid = threadIdx.x, lane = tid & 31, wid = tid >> 5;
    int brow = blockIdx.y, bcol = blockIdx.x;
    int wm = wid >> 1, wn = wid & 1;          // warp: rows wm*32, cols wn*32
    int widx = blockIdx.z;                    // 0=Wq, 1=Wk

    int r0 = tid >> 2;                        // 0..63
    int sg = (tid & 3) * 8;                   // elem offset of 16B segment

    // 6 source rows per thread (advance by k0 each slab)
    const __nv_bfloat16* src0 = g_ah + (size_t)(brow * 128 + r0) * DMODEL + sg;
    const __nv_bfloat16* src1 = g_ah + (size_t)(brow * 128 + 64 + r0) * DMODEL + sg;
    const __nv_bfloat16* src2 = g_al + (size_t)(brow * 128 + r0) * DMODEL + sg;
    const __nv_bfloat16* src3 = g_al + (size_t)(brow * 128 + 64 + r0) * DMODEL + sg;
    const __nv_bfloat16* src4 = g_wh + (size_t)widx * DMODEL * DMODEL + (size_t)(bcol * 64 + r0) * DMODEL + sg;
    const __nv_bfloat16* src5 = g_wl + (size_t)widx * DMODEL * DMODEL + (size_t)(bcol * 64 + r0) * DMODEL + sg;

    float acc[2][4][4];
    #pragma unroll
    for (int i = 0; i < 2; i++)
        #pragma unroll
        for (int j = 0; j < 4; j++)
            #pragma unroll
            for (int k = 0; k < 4; k++) acc[i][j][k] = 0.f;

    // prologue: slab 0 -> stage 0
    {
        uint32_t d = smem_u32(smp) + (uint32_t)(r0 * GLDS + sg) * 2;
        cpasync16(d,                  src0);
        cpasync16(d + 64 * GLDS * 2,  src1);
        cpasync16(d + 128 * GLDS * 2, src2);
        cpasync16(d + 192 * GLDS * 2, src3);
        cpasync16(d + 256 * GLDS * 2, src4);
        cpasync16(d + 320 * GLDS * 2, src5);
        cpcommit();
    }

    for (int it = 0; it < DMODEL / 32; it++) {
        int s = it & 1;
        cpwait0();
        __syncthreads();
        if (it + 1 < DMODEL / 32) {
            int k0 = (it + 1) * 32;
            uint32_t d = smem_u32(smp) + (uint32_t)((s ^ 1) * BF_STAGE + r0 * GLDS + sg) * 2;
            cpasync16(d,                  src0 + k0);
            cpasync16(d + 64 * GLDS * 2,  src1 + k0);
            cpasync16(d + 128 * GLDS * 2, src2 + k0);
            cpasync16(d + 192 * GLDS * 2, src3 + k0);
            cpasync16(d + 256 * GLDS * 2, src4 + k0);
            cpasync16(d + 320 * GLDS * 2, src5 + k0);
            cpcommit();
        }

        const __nv_bfloat16* sm = smp + s * BF_STAGE;
        #pragma unroll
        for (int ks = 0; ks < 2; ks++) {
            uint32_t ah[2][4], al[2][4];
            #pragma unroll
            for (int mt = 0; mt < 2; mt++) {
                uint32_t a = ldm_addr2(sm, GLDS, wm * 32 + mt * 16, ks * 16, lane);
                ldm4(ah[mt], a);
                ldm4(al[mt], a + 128 * GLDS * 2);          // Al region
            }
            #pragma unroll
            for (int ng = 0; ng < 2; ng++) {
                uint32_t bm[4], bl4[4];
                uint32_t ba = ldm_addr2(sm + 256 * GLDS, GLDS, wn * 32 + ng * 16, ks * 16, lane);
                ldm4(bm, ba);
                ldm4(bl4, ba + 64 * GLDS * 2);             // Bl region
                uint32_t bh0[2] = {bm[0], bm[2]},  bh1[2] = {bm[1], bm[3]};
                uint32_t bl0[2] = {bl4[0], bl4[2]}, bl1[2] = {bl4[1], bl4[3]};
                #pragma unroll
                for (int mt = 0; mt < 2; mt++) {
                    mma16816(acc[mt][ng * 2 + 0], ah[mt], bh0);
                    mma16816(acc[mt][ng * 2 + 1], ah[mt], bh1);
                    mma16816(acc[mt][ng * 2 + 0], al[mt], bh0);
                    mma16816(acc[mt][ng * 2 + 1], al[mt], bh1);
                    mma16816(acc[mt][ng * 2 + 0], ah[mt], bl0);
                    mma16816(acc[mt][ng * 2 + 1], ah[mt], bl1);
                }
            }
        }
    }

    int g = lane >> 2, t2 = (lane & 3) * 2;
    __nv_bfloat16* dh = (widx == 0) ? g_qh : g_kh;
    __nv_bfloat16* dl = (widx == 0) ? g_ql : g_kl;
    #pragma unroll
    for (int mt = 0; mt < 2; mt++) {
        #pragma unroll
        for (int nt = 0; nt < 4; nt++) {
            int row0 = brow * 128 + wm * 32 + mt * 16 + g;
            int col  = bcol * 64 + wn * 32 + nt * 8 + t2;
            int hh = col >> 6, d = col & 63;
            #pragma unroll
            for (int rr = 0; rr < 2; rr++) {
                int r = row0 + rr * 8;
                int b = r >> 11, s = r & (SEQ - 1);
                size_t o = (((size_t)(b * NHEAD + hh) * SEQ) + s) * DHEAD + d;
                uint32_t hv, lv;
                pack_split(acc[mt][nt][rr * 2], acc[mt][nt][rr * 2 + 1], hv, lv);
                *(uint32_t*)(dh + o) = hv;
                *(uint32_t*)(dl + o) = lv;
            }
        }
    }
}

// ---------------- fp16 2-term GEMM v2: CTA 128x64, warp 32x32, 3 CTAs/SM ----------------
// stage rows: Ah[0..127] | Al[128..255] | Bh[256..319]
#define H_STAGE (320 * GLDS)
#define GS2_H (2 * H_STAGE * 2)

__global__ __launch_bounds__(256, 3) void mma_gemm_h(float* __restrict__ outp, int which)
{
    extern __shared__ __half smh[];
    int tid = threadIdx.x, lane = tid & 31, wid = tid >> 5;
    int brow = blockIdx.y, bcol = blockIdx.x;
    int wm = wid >> 1, wn = wid & 1;

    int r0 = tid >> 2;
    int sg = (tid & 3) * 8;

    const __half* src0 = (which ? g_oh : g_fh) + (size_t)(brow * 128 + r0) * DMODEL + sg;
    const __half* src1 = (which ? g_oh : g_fh) + (size_t)(brow * 128 + 64 + r0) * DMODEL + sg;
    const __half* src2 = (which ? g_ol : g_fl) + (size_t)(brow * 128 + r0) * DMODEL + sg;
    const __half* src3 = (which ? g_ol : g_fl) + (size_t)(brow * 128 + 64 + r0) * DMODEL + sg;
    const __half* src4 = (which ? g_woh : g_wvh) + (size_t)(bcol * 64 + r0) * DMODEL + sg;

    float acc[2][4][4];
    #pragma unroll
    for (int i = 0; i < 2; i++)
        #pragma unroll
        for (int j = 0; j < 4; j++)
            #pragma unroll
            for (int k = 0; k < 4; k++) acc[i][j][k] = 0.f;

    {
        uint32_t d = smem_u32(smh) + (uint32_t)(r0 * GLDS + sg) * 2;
        cpasync16(d,                  src0);
        cpasync16(d + 64 * GLDS * 2,  src1);
        cpasync16(d + 128 * GLDS * 2, src2);
        cpasync16(d + 192 * GLDS * 2, src3);
        cpasync16(d + 256 * GLDS * 2, src4);
        cpcommit();
    }

    for (int it = 0; it < DMODEL / 32; it++) {
        int s = it & 1;
        cpwait0();
        __syncthreads();
        if (it + 1 < DMODEL / 32) {
            int k0 = (it + 1) * 32;
            uint32_t d = smem_u32(smh) + (uint32_t)((s ^ 1) * H_STAGE + r0 * GLDS + sg) * 2;
            cpasync16(d,                  src0 + k0);
            cpasync16(d + 64 * GLDS * 2,  src1 + k0);
            cpasync16(d + 128 * GLDS * 2, src2 + k0);
            cpasync16(d + 192 * GLDS * 2, src3 + k0);
            cpasync16(d + 256 * GLDS * 2, src4 + k0);
            cpcommit();
        }

        const __half* sm = smh + s * H_STAGE;
        #pragma unroll
        for (int ks = 0; ks < 2; ks++) {
            uint32_t ah[2][4], al[2][4];
            #pragma unroll
            for (int mt = 0; mt < 2; mt++) {
                uint32_t a = ldm_addr2(sm, GLDS, wm * 32 + mt * 16, ks * 16, lane);
                ldm4(ah[mt], a);
                ldm4(al[mt], a + 128 * GLDS * 2);
            }
            #pragma unroll
            for (int ng = 0; ng < 2; ng++) {
                uint32_t bm[4];
                uint32_t ba = ldm_addr2(sm + 256 * GLDS, GLDS, wn * 32 + ng * 16, ks * 16, lane);
                ldm4(bm, ba);
                uint32_t bh0[2] = {bm[0], bm[2]}, bh1[2] = {bm[1], bm[3]};
                #pragma unroll
                for (int mt = 0; mt < 2; mt++) {
                    mma16816h(acc[mt][ng * 2 + 0], ah[mt], bh0);
                    mma16816h(acc[mt][ng * 2 + 1], ah[mt], bh1);
                    mma16816h(acc[mt][ng * 2 + 0], al[mt], bh0);
                    mma16816h(acc[mt][ng * 2 + 1], al[mt], bh1);
                }
            }
        }
    }

    int g = lane >> 2, t2 = (lane & 3) * 2;
    #pragma unroll
    for (int mt = 0; mt < 2; mt++) {
        #pragma unroll
        for (int nt = 0; nt < 4; nt++) {
            int row0 = brow * 128 + wm * 32 + mt * 16 + g;
            int col  = bcol * 64 + wn * 32 + nt * 8 + t2;
            if (which == 1) {
                float2 p0 = {acc[mt][nt][0], acc[mt][nt][1]};
                float2 p1 = {acc[mt][nt][2], acc[mt][nt][3]};
                *(float2*)(outp + (size_t)row0 * DMODEL + col) = p0;
                *(float2*)(outp + (size_t)(row0 + 8) * DMODEL + col) = p1;
            } else {
                int hh = col >> 6, d = col & 63;
                #pragma unroll
                for (int rr = 0; rr < 2; rr++) {
                    int r = row0 + rr * 8;
                    int b = r >> 11, s = r & (SEQ - 1);
                    size_t o = (((size_t)(b * NHEAD + hh) * SEQ) + s) * DHEAD + d;
                    __half2 v = __floats2half2_rn(acc[mt][nt][rr * 2], acc[mt][nt][rr * 2 + 1]);
                    *(__half2*)(g_vh + o) = v;
                }
            }
        }
    }
}

// ---------------- flash attention: QK bf16 3-term, PV fp16 2-term (unchanged) ----------------
#define QLDS 72
#define KVSTAGE (3 * 64 * QLDS)   // Kh | Kl | Vh
#define ATT_SMEM (2*128*QLDS*2 + 2*KVSTAGE*2 + 2*192*4)

__global__ __launch_bounds__(256, 2) void mma_attn()
{
    extern __shared__ char smemraw[];
    __nv_bfloat16* sQh = (__nv_bfloat16*)smemraw;          // 128 x 72
    __nv_bfloat16* sQl = sQh + 128 * QLDS;
    __nv_bfloat16* sKV = sQl + 128 * QLDS;                 // 2 stages x (Kh|Kl|Vh)
    float* sBias = (float*)(sKV + 2 * KVSTAGE);            // 2 x 192

    int tid = threadIdx.x, lane = tid & 31, wid = tid >> 5;
    int b = blockIdx.z, h = blockIdx.y, q0 = blockIdx.x * 128;
    size_t bh = (size_t)(b * NHEAD + h) * SEQ;

    const void* kvsrc[3] = {(const void*)g_kh, (const void*)g_kl, (const void*)g_vh};

    #pragma unroll
    for (int t = 0; t < 8; t++) {
        int gid = tid + t * 256;
        int buf = gid >> 10, rem = gid & 1023, row = rem >> 3, seg = rem & 7;
        const __nv_bfloat16* src = (buf ? g_ql : g_qh) + (bh + q0 + row) * DHEAD + seg * 8;
        *(uint4*)((buf ? sQl : sQh) + row * QLDS + seg * 8) = *(const uint4*)src;
    }

    int vbuf[6], vrow[6], vseg[6];
    #pragma unroll
    for (int t = 0; t < 6; t++) {
        int gid = tid + t * 256;
        vbuf[t] = gid >> 9; vrow[t] = (gid >> 3) & 63; vseg[t] = gid & 7;
    }

    #pragma unroll
    for (int t = 0; t < 6; t++) {
        uint32_t dst = smem_u32(sKV + vbuf[t] * (64 * QLDS) + vrow[t] * QLDS + vseg[t] * 8);
        cpasync16(dst, (const __nv_bfloat16*)kvsrc[vbuf[t]] + (bh + vrow[t]) * DHEAD + vseg[t] * 8);
    }
    cpcommit();
    if (tid < 191)
        sBias[tid] = g_bias[h * NBIAS + (SEQ - 1) - q0 - 127 + tid];
    __syncthreads();

    uint32_t qh[4][4], ql[4][4];
    #pragma unroll
    for (int ks = 0; ks < 4; ks++) {
        uint32_t a = ldm_addr2(sQh, QLDS, wid * 16, ks * 16, lane);
        ldm4(qh[ks], a);
        ldm4(ql[ks], a + 128 * QLDS * 2);
    }

    int g = lane >> 2, t2 = (lane & 3) * 2;
    int qloc0 = wid * 16 + g, qloc1 = qloc0 + 8;
    float m0 = -1e30f, m1 = -1e30f, l0 = 0.f, l1 = 0.f;
    float acco[8][4];
    #pragma unroll
    for (int i = 0; i < 8; i++)
        #pragma unroll
        for (int j = 0; j < 4; j++) acco[i][j] = 0.f;

    for (int kb = 0; kb < SEQ / 64; kb++) {
        int s = kb & 1;
        cpwait0();
        __syncthreads();
        if (kb + 1 < SEQ / 64) {
            #pragma unroll
            for (int t = 0; t < 6; t++) {
                uint32_t dst = smem_u32(sKV + (s ^ 1) * KVSTAGE + vbuf[t] * (64 * QLDS) + vrow[t] * QLDS + vseg[t] * 8);
                cpasync16(dst, (const __nv_bfloat16*)kvsrc[vbuf[t]] + (bh + (kb + 1) * 64 + vrow[t]) * DHEAD + vseg[t] * 8);
            }
            cpcommit();
            if (tid < 191)
                sBias[(s ^ 1) * 192 + tid] = g_bias[h * NBIAS + (SEQ - 1) + (kb + 1) * 64 - q0 - 127 + tid];
        }

        const __nv_bfloat16* sKh = sKV + s * KVSTAGE;
        const float* bias = sBias + s * 192;

        float accs[8][4];
        #pragma unroll
        for (int i = 0; i < 8; i++)
            #pragma unroll
            for (int j = 0; j < 4; j++) accs[i][j] = 0.f;

        #pragma unroll
        for (int ks = 0; ks < 4; ks++) {
            #pragma unroll
            for (int ng = 0; ng < 4; ng++) {
                uint32_t km[4], kl4[4];
                uint32_t ka = ldm_addr2(sKh, QLDS, ng * 16, ks * 16, lane);
                ldm4(km, ka);
                ldm4(kl4, ka + 64 * QLDS * 2);
                uint32_t kh0[2] = {km[0], km[2]},  kh1[2] = {km[1], km[3]};
                uint32_t kl0[2] = {kl4[0], kl4[2]}, kl1[2] = {kl4[1], kl4[3]};
                mma16816(accs[ng * 2 + 0], qh[ks], kh0);
                mma16816(accs[ng * 2 + 1], qh[ks], kh1);
                mma16816(accs[ng * 2 + 0], ql[ks], kh0);
                mma16816(accs[ng * 2 + 1], ql[ks], kh1);
                mma16816(accs[ng * 2 + 0], qh[ks], kl0);
                mma16816(accs[ng * 2 + 1], qh[ks], kl1);
            }
        }

        float rmax0 = -1e30f, rmax1 = -1e30f;
        #pragma unroll
        for (int nt = 0; nt < 8; nt++) {
            int c = nt * 8 + t2;
            accs[nt][0] += bias[c + 127 - qloc0];
            accs[nt][1] += bias[c + 128 - qloc0];
            accs[nt][2] += bias[c + 127 - qloc1];
            accs[nt][3] += bias[c + 128 - qloc1];
            rmax0 = fmaxf(rmax0, fmaxf(accs[nt][0], accs[nt][1]));
            rmax1 = fmaxf(rmax1, fmaxf(accs[nt][2], accs[nt][3]));
        }
        rmax0 = fmaxf(rmax0, __shfl_xor_sync(0xffffffffu, rmax0, 1, 4));
        rmax0 = fmaxf(rmax0, __shfl_xor_sync(0xffffffffu, rmax0, 2, 4));
        rmax1 = fmaxf(rmax1, __shfl_xor_sync(0xffffffffu, rmax1, 1, 4));
        rmax1 = fmaxf(rmax1, __shfl_xor_sync(0xffffffffu, rmax1, 2, 4));
        float mn0 = fmaxf(m0, rmax0), mn1 = fmaxf(m1, rmax1);
        float corr0 = __expf(m0 - mn0), corr1 = __expf(m1 - mn1);
        float sum0 = 0.f, sum1 = 0.f;
        #pragma unroll
        for (int nt = 0; nt < 8; nt++) {
            accs[nt][0] = __expf(accs[nt][0] - mn0);
            accs[nt][1] = __expf(accs[nt][1] - mn0);
            accs[nt][2] = __expf(accs[nt][2] - mn1);
            accs[nt][3] = __expf(accs[nt][3] - mn1);
            sum0 += accs[nt][0] + accs[nt][1];
            sum1 += accs[nt][2] + accs[nt][3];
        }
        sum0 += __shfl_xor_sync(0xffffffffu, sum0, 1, 4);
        sum0 += __shfl_xor_sync(0xffffffffu, sum0, 2, 4);
        sum1 += __shfl_xor_sync(0xffffffffu, sum1, 1, 4);
        sum1 += __shfl_xor_sync(0xffffffffu, sum1, 2, 4);
        m0 = mn0; m1 = mn1;
        l0 = l0 * corr0 + sum0;
        l1 = l1 * corr1 + sum1;
        #pragma unroll
        for (int nt = 0; nt < 8; nt++) {
            acco[nt][0] *= corr0; acco[nt][1] *= corr0;
            acco[nt][2] *= corr1; acco[nt][3] *= corr1;
        }

        const __nv_bfloat16* sVh = sKh + 2 * 64 * QLDS;
        #pragma unroll
        for (int ks = 0; ks < 4; ks++) {
            uint32_t ph[4], pl[4];
            pack_split_h(accs[2 * ks][0],     accs[2 * ks][1],     ph[0], pl[0]);
            pack_split_h(accs[2 * ks][2],     accs[2 * ks][3],     ph[1], pl[1]);
            pack_split_h(accs[2 * ks + 1][0], accs[2 * ks + 1][1], ph[2], pl[2]);
            pack_split_h(accs[2 * ks + 1][2], accs[2 * ks + 1][3], ph[3], pl[3]);
            #pragma unroll
            for (int dg = 0; dg < 4; dg++) {
                uint32_t vm[4];
                uint32_t va = ldm_addr2(sVh, QLDS, ks * 16, dg * 16, lane);
                ldm4t(vm, va);
                uint32_t vh0[2] = {vm[0], vm[1]}, vh1[2] = {vm[2], vm[3]};
                mma16816h(acco[dg * 2 + 0], ph, vh0);
                mma16816h(acco[dg * 2 + 1], ph, vh1);
                mma16816h(acco[dg * 2 + 0], pl, vh0);
                mma16816h(acco[dg * 2 + 1], pl, vh1);
            }
        }
    }

    float inv0 = 1.0f / l0, inv1 = 1.0f / l1;
    int row0 = b * SEQ + q0 + wid * 16 + g;
    #pragma unroll
    for (int dt = 0; dt < 8; dt++) {
        int d = h * DHEAD + dt * 8 + t2;
        uint32_t hv, lv;
        pack_split_h(acco[dt][0] * inv0, acco[dt][1] * inv0, hv, lv);
        *(uint32_t*)(g_oh + (size_t)row0 * DMODEL + d) = hv;
        *(uint32_t*)(g_ol + (size_t)row0 * DMODEL + d) = lv;
        pack_split_h(acco[dt][2] * inv1, acco[dt][3] * inv1, hv, lv);
        *(uint32_t*)(g_oh + (size_t)(row0 + 8) * DMODEL + d) = hv;
        *(uint32_t*)(g_ol + (size_t)(row0 + 8) * DMODEL + d) = lv;
    }
}

// ---------------- launch ----------------
extern "C" void kernel_launch(void* const* d_in, const int* in_sizes, int n_in,
                              void* d_out, int out_size)
{
    const float* hs  = (const float*)d_in[0];
    const float* Wq  = (const float*)d_in[1];
    const float* Wk  = (const float*)d_in[2];
    const float* Wv  = (const float*)d_in[3];
    const float* Wo  = (const float*)d_in[4];
    const float* rel = (const float*)d_in[5];
    float* out = (float*)d_out;

    cudaFuncSetAttribute(mma_gemm_bf, cudaFuncAttributeMaxDynamicSharedMemorySize, GS2_BF);
    cudaFuncSetAttribute(mma_gemm_h,  cudaFuncAttributeMaxDynamicSharedMemorySize, GS2_H);
    cudaFuncSetAttribute(mma_attn,    cudaFuncAttributeMaxDynamicSharedMemorySize, ATT_SMEM);

    bias_kernel<<<16, 256>>>(rel);                                   // launch 0
    split_a_kernel<<<(MROWS * DMODEL) / (256 * 4), 256>>>(hs);       // launch 1
    dim3 wgrid(32, 32, 4);
    wsplit_kernel<<<wgrid, 256>>>(Wq, Wk, Wv, Wo);                   // launch 2

    dim3 qkgrid(DMODEL / 64, MROWS / 128, 2);                        // (16, 32, 2)
    mma_gemm_bf<<<qkgrid, 256, GS2_BF>>>();                          // launch 3: Wq,Wk

    dim3 ggrid(DMODEL / 64, MROWS / 128);                            // (16, 32)
    mma_gemm_h<<<ggrid, 256, GS2_H>>>(out, 0);                       // launch 4: Wv -> fp16 v

    dim3 agrid(SEQ / 128, NHEAD, BATCH);                             // (16, 16, 2)
    mma_attn<<<agrid, 256, ATT_SMEM>>>();                            // launch 5

    mma_gemm_h<<<ggrid, 256, GS2_H>>>(out, 1);                       // launch 6: Wo -> fp32 out
}